// round 3
// baseline (speedup 1.0000x reference)
#include <cuda_runtime.h>
#include <cuda_bf16.h>
#include <math.h>

#define BB 8
#define S1 4096
#define S2 256
#define NH 16
#define HD 64
#define QD 1024
#define KVD 2048
#define EPSF 1e-6f
#define SCALEF 0.125f
#define AR 128

#define PADK 40                    // bf16 elements per smem row (32 + 8 pad)
#define OPELEMS (128 * PADK)       // 5120 bf16 per operand tile
#define STAGE_ELEMS (4 * OPELEMS)  // Ah, Al, Wh, Wl
#define STAGES 4

// ---------------- scratch (device globals; no allocation allowed) ----------
__device__ float g_q[(size_t)BB * S1 * QD];
__device__ float g_kv[(size_t)BB * S2 * KVD];
__device__ __nv_bfloat16 g_xh[(size_t)BB * S1 * QD];
__device__ __nv_bfloat16 g_xl[(size_t)BB * S1 * QD];
__device__ __nv_bfloat16 g_yh[(size_t)BB * S2 * KVD];
__device__ __nv_bfloat16 g_yl[(size_t)BB * S2 * KVD];
__device__ __nv_bfloat16 g_wqh[(size_t)QD * QD];
__device__ __nv_bfloat16 g_wql[(size_t)QD * QD];
__device__ __nv_bfloat16 g_wkvh[(size_t)2 * QD * KVD];
__device__ __nv_bfloat16 g_wkvl[(size_t)2 * QD * KVD];
__device__ __nv_bfloat16 g_woh[(size_t)QD * QD];
__device__ __nv_bfloat16 g_wol[(size_t)QD * QD];
__device__ __nv_bfloat16 g_atth[(size_t)BB * S1 * QD];
__device__ __nv_bfloat16 g_attl[(size_t)BB * S1 * QD];

// ---------------------------------------------------------------------------
__device__ __forceinline__ void mma16816(float* c, const unsigned* a, const unsigned* b)
{
    asm volatile(
        "mma.sync.aligned.m16n8k16.row.col.f32.bf16.bf16.f32 "
        "{%0,%1,%2,%3}, {%4,%5,%6,%7}, {%8,%9}, {%0,%1,%2,%3};"
        : "+f"(c[0]), "+f"(c[1]), "+f"(c[2]), "+f"(c[3])
        : "r"(a[0]), "r"(a[1]), "r"(a[2]), "r"(a[3]), "r"(b[0]), "r"(b[1]));
}

__device__ __forceinline__ void cp16(__nv_bfloat16* dst, const __nv_bfloat16* src)
{
    unsigned d = (unsigned)__cvta_generic_to_shared(dst);
    asm volatile("cp.async.ca.shared.global [%0], [%1], 16;\n" :: "r"(d), "l"(src));
}
__device__ __forceinline__ void cp_commit() { asm volatile("cp.async.commit_group;\n" ::: "memory"); }
__device__ __forceinline__ void cp_wait2() { asm volatile("cp.async.wait_group 2;\n" ::: "memory"); }

__device__ __forceinline__ unsigned pack_bf16(__nv_bfloat16 lo, __nv_bfloat16 hi)
{
    return (unsigned)__bfloat16_as_ushort(lo) | ((unsigned)__bfloat16_as_ushort(hi) << 16);
}

// ---------------------------------------------------------------------------
// Split pass: fp32 -> (bf16 hi, bf16 lo).  n % 4 == 0.
// ---------------------------------------------------------------------------
__global__ void split_hl(const float* __restrict__ in,
                         __nv_bfloat16* __restrict__ hi, __nv_bfloat16* __restrict__ lo,
                         int n4)
{
    int i = blockIdx.x * blockDim.x + threadIdx.x;
    if (i >= n4) return;
    float4 v = ((const float4*)in)[i];
    float va[4] = {v.x, v.y, v.z, v.w};
    __nv_bfloat16 h[4], l[4];
#pragma unroll
    for (int j = 0; j < 4; j++) {
        h[j] = __float2bfloat16(va[j]);
        l[j] = __float2bfloat16(va[j] - __bfloat162float(h[j]));
    }
    ((uint2*)hi)[i] = make_uint2(pack_bf16(h[0], h[1]), pack_bf16(h[2], h[3]));
    ((uint2*)lo)[i] = make_uint2(pack_bf16(l[0], l[1]), pack_bf16(l[2], l[3]));
}

// ---------------------------------------------------------------------------
// Pipelined bf16 split-precision GEMM: C = A @ W^T + bias (3 MMA passes).
// A,W pre-split into hi/lo bf16, row-major (M,K)/(N,K). Tile 128x128, BK=32,
// 4-stage cp.async pipeline. 256 threads = 8 warps (4 over M x 2 over N).
// ---------------------------------------------------------------------------
__global__ __launch_bounds__(256) void gemm_bias_tc(
    const __nv_bfloat16* __restrict__ Ah, const __nv_bfloat16* __restrict__ Al,
    const __nv_bfloat16* __restrict__ Wh, const __nv_bfloat16* __restrict__ Wl,
    const float* __restrict__ bias, float* __restrict__ C,
    int M, int N, int K)
{
    extern __shared__ __nv_bfloat16 smp[];

    int tid = threadIdx.x;
    int wid = tid >> 5, lane = tid & 31;
    int wm = wid & 3, wn = wid >> 2;
    int g = lane >> 2, t = lane & 3;

    const __nv_bfloat16* Abh = Ah + (size_t)blockIdx.y * 128 * K;
    const __nv_bfloat16* Abl = Al + (size_t)blockIdx.y * 128 * K;
    const __nv_bfloat16* Wbh = Wh + (size_t)blockIdx.x * 128 * K;
    const __nv_bfloat16* Wbl = Wl + (size_t)blockIdx.x * 128 * K;

    float acc[2][8][4];
#pragma unroll
    for (int mi = 0; mi < 2; mi++)
#pragma unroll
        for (int ni = 0; ni < 8; ni++)
#pragma unroll
            for (int r = 0; r < 4; r++) acc[mi][ni][r] = 0.0f;

    // chunk coords for this thread (2 chunks of 16B per operand per stage)
    int crow[2], cseg[2];
#pragma unroll
    for (int i = 0; i < 2; i++) {
        int c = tid + i * 256;
        crow[i] = c >> 2;
        cseg[i] = (c & 3) * 8;
    }

#define ISSUE_STAGE(s, kt)                                              \
    do {                                                                \
        __nv_bfloat16* base = smp + (s) * STAGE_ELEMS;                  \
        _Pragma("unroll")                                               \
        for (int i = 0; i < 2; i++) {                                   \
            int soff = crow[i] * PADK + cseg[i];                        \
            size_t goff = (size_t)crow[i] * K + (kt) + cseg[i];         \
            cp16(base + soff, Abh + goff);                              \
            cp16(base + OPELEMS + soff, Abl + goff);                    \
            cp16(base + 2 * OPELEMS + soff, Wbh + goff);                \
            cp16(base + 3 * OPELEMS + soff, Wbl + goff);                \
        }                                                               \
    } while (0)

    int ktiles = K >> 5;
#pragma unroll
    for (int s = 0; s < STAGES - 1; s++) {
        ISSUE_STAGE(s, s * 32);
        cp_commit();
    }

    for (int ki = 0; ki < ktiles; ki++) {
        cp_wait2();
        __syncthreads();
        int nk = ki + STAGES - 1;
        if (nk < ktiles) ISSUE_STAGE(nk & (STAGES - 1), nk * 32);
        cp_commit();

        const __nv_bfloat16* As_hi = smp + (ki & (STAGES - 1)) * STAGE_ELEMS;
        const __nv_bfloat16* As_lo = As_hi + OPELEMS;
        const __nv_bfloat16* Bs_hi = As_hi + 2 * OPELEMS;
        const __nv_bfloat16* Bs_lo = As_hi + 3 * OPELEMS;

#pragma unroll
        for (int k0 = 0; k0 < 32; k0 += 16) {
            unsigned ah[2][4], al[2][4];
#pragma unroll
            for (int mi = 0; mi < 2; mi++) {
                int rb = wm * 32 + mi * 16;
                int o00 = (rb + g) * PADK + k0 + 2 * t;
                int o10 = (rb + g + 8) * PADK + k0 + 2 * t;
                ah[mi][0] = *(const unsigned*)&As_hi[o00];
                ah[mi][1] = *(const unsigned*)&As_hi[o10];
                ah[mi][2] = *(const unsigned*)&As_hi[o00 + 8];
                ah[mi][3] = *(const unsigned*)&As_hi[o10 + 8];
                al[mi][0] = *(const unsigned*)&As_lo[o00];
                al[mi][1] = *(const unsigned*)&As_lo[o10];
                al[mi][2] = *(const unsigned*)&As_lo[o00 + 8];
                al[mi][3] = *(const unsigned*)&As_lo[o10 + 8];
            }
#pragma unroll
            for (int ni = 0; ni < 8; ni++) {
                int nb = wn * 64 + ni * 8;
                int ob = (nb + g) * PADK + k0 + 2 * t;
                unsigned bh[2], bl[2];
                bh[0] = *(const unsigned*)&Bs_hi[ob];
                bh[1] = *(const unsigned*)&Bs_hi[ob + 8];
                bl[0] = *(const unsigned*)&Bs_lo[ob];
                bl[1] = *(const unsigned*)&Bs_lo[ob + 8];
#pragma unroll
                for (int mi = 0; mi < 2; mi++) {
                    mma16816(acc[mi][ni], ah[mi], bh);
                    mma16816(acc[mi][ni], al[mi], bh);
                    mma16816(acc[mi][ni], ah[mi], bl);
                }
            }
        }
        __syncthreads();
    }

    // epilogue: bias + fp32 store
#pragma unroll
    for (int mi = 0; mi < 2; mi++) {
#pragma unroll
        for (int ni = 0; ni < 8; ni++) {
            int col = blockIdx.x * 128 + wn * 64 + ni * 8 + 2 * t;
            float b0 = bias[col], b1 = bias[col + 1];
            size_t row0 = (size_t)blockIdx.y * 128 + wm * 32 + mi * 16 + g;
            *(float2*)(C + row0 * N + col) =
                make_float2(acc[mi][ni][0] + b0, acc[mi][ni][1] + b1);
            *(float2*)(C + (row0 + 8) * N + col) =
                make_float2(acc[mi][ni][2] + b0, acc[mi][ni][3] + b1);
        }
    }
}

// ---------------------------------------------------------------------------
// LayerNorm + 2D RoPE on Q, in place. One warp per (b, s, h).
// ---------------------------------------------------------------------------
__global__ void ln_rope_q(float* __restrict__ q,
                          const float* __restrict__ g, const float* __restrict__ bt)
{
    int gw = (blockIdx.x * blockDim.x + threadIdx.x) >> 5;
    int lane = threadIdx.x & 31;
    if (gw >= BB * S1 * NH) return;
    float2* p = (float2*)(q + (size_t)gw * HD);
    float2 v = p[lane];
    float sum = v.x + v.y;
    float sq = v.x * v.x + v.y * v.y;
#pragma unroll
    for (int o = 16; o; o >>= 1) {
        sum += __shfl_xor_sync(0xffffffffu, sum, o);
        sq  += __shfl_xor_sync(0xffffffffu, sq, o);
    }
    float mu = sum * (1.0f / HD);
    float var = sq * (1.0f / HD) - mu * mu;
    float rstd = rsqrtf(var + EPSF);
    float e  = (v.x - mu) * rstd * g[2 * lane]     + bt[2 * lane];
    float od = (v.y - mu) * rstd * g[2 * lane + 1] + bt[2 * lane + 1];

    int s = (gw / NH) & (S1 - 1);
    int hh = s >> 6, ww = s & 63;
    int t = lane >> 1;
    float inv = exp10f(-0.25f * (float)t);
    float ang = ((lane & 1) ? (float)ww : (float)hh) * inv;
    float n = rintf(ang * 0.15915494309189535f);
    ang -= n * 6.283185307179586f;
    float sn, cs;
    sincosf(ang, &sn, &cs);
    p[lane] = make_float2(e * cs - od * sn, e * sn + od * cs);
}

__global__ void ln_k(float* __restrict__ kv,
                     const float* __restrict__ g, const float* __restrict__ bt)
{
    int gw = (blockIdx.x * blockDim.x + threadIdx.x) >> 5;
    int lane = threadIdx.x & 31;
    if (gw >= BB * S2 * NH) return;
    int row = gw / NH, h = gw % NH;
    float2* p = (float2*)(kv + (size_t)row * KVD + h * HD);
    float2 v = p[lane];
    float sum = v.x + v.y;
    float sq = v.x * v.x + v.y * v.y;
#pragma unroll
    for (int o = 16; o; o >>= 1) {
        sum += __shfl_xor_sync(0xffffffffu, sum, o);
        sq  += __shfl_xor_sync(0xffffffffu, sq, o);
    }
    float mu = sum * (1.0f / HD);
    float var = sq * (1.0f / HD) - mu * mu;
    float rstd = rsqrtf(var + EPSF);
    float e  = (v.x - mu) * rstd * g[2 * lane]     + bt[2 * lane];
    float od = (v.y - mu) * rstd * g[2 * lane + 1] + bt[2 * lane + 1];
    p[lane] = make_float2(e, od);
}

// ---------------------------------------------------------------------------
// Attention (fp32 SIMT). Output written directly as bf16 hi/lo for GEMM3.
// ---------------------------------------------------------------------------
__global__ __launch_bounds__(256) void attention_kernel(
    const float* __restrict__ q, const float* __restrict__ kv,
    __nv_bfloat16* __restrict__ oh, __nv_bfloat16* __restrict__ ol)
{
    extern __shared__ float sm[];
    float* Qs = sm;
    float* Ks = sm + AR * HD;
    float* Ss = Ks + S2 * 65;
    int bh = blockIdx.y;
    int b = bh >> 4, h = bh & 15;
    int r0 = blockIdx.x * AR;
    int tid = threadIdx.x;

    for (int i = tid; i < AR * HD; i += 256) {
        int r = i >> 6, d = i & 63;
        Qs[i] = q[(((size_t)b * S1 + r0 + r) * NH + h) * HD + d];
    }
    for (int i = tid; i < S2 * HD; i += 256) {
        int k = i >> 6, d = i & 63;
        Ks[k * 65 + d] = kv[((size_t)b * S2 + k) * KVD + h * HD + d];
    }
    __syncthreads();

    float kreg[64];
#pragma unroll
    for (int d = 0; d < 64; d++) kreg[d] = Ks[tid * 65 + d];

    for (int r = 0; r < AR; r += 2) {
        const float* q0 = Qs + r * 64;
        const float* q1 = q0 + 64;
        float a0 = 0, a1 = 0, c0 = 0, c1 = 0;
#pragma unroll
        for (int d = 0; d < 64; d += 2) {
            a0 += q0[d] * kreg[d];     a1 += q0[d + 1] * kreg[d + 1];
            c0 += q1[d] * kreg[d];     c1 += q1[d + 1] * kreg[d + 1];
        }
        Ss[r * 256 + tid]       = (a0 + a1) * SCALEF;
        Ss[(r + 1) * 256 + tid] = (c0 + c1) * SCALEF;
    }
    __syncthreads();

    int wid = tid >> 5, lane = tid & 31;
    for (int r = wid; r < AR; r += 8) {
        float* srow = Ss + r * 256;
        float vals[8];
        float m = -1e30f;
#pragma unroll
        for (int i = 0; i < 8; i++) { vals[i] = srow[lane + 32 * i]; m = fmaxf(m, vals[i]); }
#pragma unroll
        for (int o = 16; o; o >>= 1) m = fmaxf(m, __shfl_xor_sync(0xffffffffu, m, o));
        float l = 0;
#pragma unroll
        for (int i = 0; i < 8; i++) { vals[i] = __expf(vals[i] - m); l += vals[i]; }
#pragma unroll
        for (int o = 16; o; o >>= 1) l += __shfl_xor_sync(0xffffffffu, l, o);
        float rl = 1.0f / l;
#pragma unroll
        for (int i = 0; i < 8; i++) srow[lane + 32 * i] = vals[i] * rl;
    }
    __syncthreads();

    for (int i = tid; i < S2 * HD; i += 256) {
        int k = i >> 6, d = i & 63;
        Ks[k * 65 + d] = kv[((size_t)b * S2 + k) * KVD + QD + h * HD + d];
    }
    __syncthreads();

    int d0 = lane, d1 = lane + 32;
    for (int i = 0; i < 16; i++) {
        int r = wid + 8 * i;
        const float* srow = Ss + r * 256;
        float acc0 = 0, acc1 = 0;
#pragma unroll 8
        for (int k = 0; k < 256; k++) {
            float pv = srow[k];
            acc0 += pv * Ks[k * 65 + d0];
            acc1 += pv * Ks[k * 65 + d1];
        }
        size_t ob = (((size_t)b * S1 + r0 + r) * NH + h) * HD;
        __nv_bfloat16 h0 = __float2bfloat16(acc0);
        __nv_bfloat16 h1 = __float2bfloat16(acc1);
        oh[ob + d0] = h0;
        oh[ob + d1] = h1;
        ol[ob + d0] = __float2bfloat16(acc0 - __bfloat162float(h0));
        ol[ob + d1] = __float2bfloat16(acc1 - __bfloat162float(h1));
    }
}

// ---------------------------------------------------------------------------
extern "C" void kernel_launch(void* const* d_in, const int* in_sizes, int n_in,
                              void* d_out, int out_size)
{
    (void)in_sizes; (void)n_in; (void)out_size;
    const float* x   = (const float*)d_in[0];
    const float* y   = (const float*)d_in[1];
    const float* wq  = (const float*)d_in[2];
    const float* bq  = (const float*)d_in[3];
    const float* wkv = (const float*)d_in[4];
    const float* bkv = (const float*)d_in[5];
    const float* wo  = (const float*)d_in[6];
    const float* bo  = (const float*)d_in[7];
    const float* qng = (const float*)d_in[8];
    const float* qnb = (const float*)d_in[9];
    const float* kng = (const float*)d_in[10];
    const float* knb = (const float*)d_in[11];
    float* out = (float*)d_out;

    float *qbuf, *kvbuf;
    __nv_bfloat16 *xh, *xl, *yh, *yl, *wqh, *wql, *wkvh, *wkvl, *woh, *wol, *atth, *attl;
    cudaGetSymbolAddress((void**)&qbuf, g_q);
    cudaGetSymbolAddress((void**)&kvbuf, g_kv);
    cudaGetSymbolAddress((void**)&xh, g_xh);   cudaGetSymbolAddress((void**)&xl, g_xl);
    cudaGetSymbolAddress((void**)&yh, g_yh);   cudaGetSymbolAddress((void**)&yl, g_yl);
    cudaGetSymbolAddress((void**)&wqh, g_wqh); cudaGetSymbolAddress((void**)&wql, g_wql);
    cudaGetSymbolAddress((void**)&wkvh, g_wkvh); cudaGetSymbolAddress((void**)&wkvl, g_wkvl);
    cudaGetSymbolAddress((void**)&woh, g_woh); cudaGetSymbolAddress((void**)&wol, g_wol);
    cudaGetSymbolAddress((void**)&atth, g_atth); cudaGetSymbolAddress((void**)&attl, g_attl);

    // 0) split inputs to bf16 hi/lo
    {
        int n;
        n = BB * S1 * QD / 4;   split_hl<<<(n + 255) / 256, 256>>>(x, xh, xl, n);
        n = BB * S2 * KVD / 4;  split_hl<<<(n + 255) / 256, 256>>>(y, yh, yl, n);
        n = QD * QD / 4;        split_hl<<<(n + 255) / 256, 256>>>(wq, wqh, wql, n);
        n = 2 * QD * KVD / 4;   split_hl<<<(n + 255) / 256, 256>>>(wkv, wkvh, wkvl, n);
        n = QD * QD / 4;        split_hl<<<(n + 255) / 256, 256>>>(wo, woh, wol, n);
    }

    size_t gsmem = (size_t)STAGES * STAGE_ELEMS * sizeof(__nv_bfloat16); // 163840
    cudaFuncSetAttribute(gemm_bias_tc, cudaFuncAttributeMaxDynamicSharedMemorySize, (int)gsmem);

    // 1) Q = x @ wq^T + bq
    gemm_bias_tc<<<dim3(QD / 128, (BB * S1) / 128), 256, gsmem>>>(
        xh, xl, wqh, wql, bq, qbuf, BB * S1, QD, QD);
    // 2) KV = y @ wkv^T + bkv
    gemm_bias_tc<<<dim3(KVD / 128, (BB * S2) / 128), 256, gsmem>>>(
        yh, yl, wkvh, wkvl, bkv, kvbuf, BB * S2, KVD, KVD);
    // 3) LN + RoPE on Q
    ln_rope_q<<<(BB * S1 * NH) / 4, 128>>>(qbuf, qng, qnb);
    // 4) LN on K
    ln_k<<<(BB * S2 * NH) / 4, 128>>>(kvbuf, kng, knb);
    // 5) attention (writes bf16 hi/lo)
    {
        size_t smem = (size_t)(AR * HD + S2 * 65 + AR * S2) * sizeof(float);
        cudaFuncSetAttribute(attention_kernel,
                             cudaFuncAttributeMaxDynamicSharedMemorySize, (int)smem);
        attention_kernel<<<dim3(S1 / AR, BB * NH), 256, smem>>>(qbuf, kvbuf, atth, attl);
    }
    // 6) out = att @ wo^T + bo
    gemm_bias_tc<<<dim3(QD / 128, (BB * S1) / 128), 256, gsmem>>>(
        atth, attl, woh, wol, bo, out, BB * S1, QD, QD);
}

// round 8
// speedup vs baseline: 1.6790x; 1.6790x over previous
#include <cuda_runtime.h>
#include <cuda_fp16.h>
#include <math.h>

#define BB 8
#define S1 4096
#define S2 256
#define NH 16
#define HD 64
#define QD 1024
#define KVD 2048
#define EPSF 1e-6f
#define SCALEF 0.125f
#define AR 128

// Scratch (device globals — no allocation allowed)
__device__ float g_q[(size_t)BB * S1 * QD];
__device__ float g_kv[(size_t)BB * S2 * KVD];
__device__ float g_att[(size_t)BB * S1 * QD];

// ---------------------------------------------------------------------------
// fp16 2-pass split tensor-core GEMM:  C = A @ W^T + bias
// A:(M,K) fp32 row-major, W:(N,K) fp32 row-major, C:(M,N) fp32.
// A = ah + al (fp16 pair, ~22 mantissa bits); W rounded to fp16 (bh).
// D = ah*bh + al*bh  (dropped a*bl ~ 2^-12 relative).
// Tile 128x128, BK=32, 256 threads (8 warps: 4 over M x 2 over N),
// warp tile 32x64 -> 2x8 m16n8k16 fragments. Register prefetch of next chunk.
// ---------------------------------------------------------------------------
#define PADK 40  // 32 + 8 halves padding: conflict-free fragment loads

__device__ __forceinline__ void mma16816f(float* c, const unsigned* a, const unsigned* b)
{
    asm volatile(
        "mma.sync.aligned.m16n8k16.row.col.f32.f16.f16.f32 "
        "{%0,%1,%2,%3}, {%4,%5,%6,%7}, {%8,%9}, {%0,%1,%2,%3};"
        : "+f"(c[0]), "+f"(c[1]), "+f"(c[2]), "+f"(c[3])
        : "r"(a[0]), "r"(a[1]), "r"(a[2]), "r"(a[3]), "r"(b[0]), "r"(b[1]));
}

__device__ __forceinline__ unsigned pack_h2(__half lo, __half hi)
{
    return (unsigned)__half_as_ushort(lo) | ((unsigned)__half_as_ushort(hi) << 16);
}

__global__ __launch_bounds__(256) void gemm_bias_tc(
    const float* __restrict__ A, const float* __restrict__ W,
    const float* __restrict__ bias, float* __restrict__ C,
    int M, int N, int K)
{
    __shared__ __half As_hi[128 * PADK];
    __shared__ __half As_lo[128 * PADK];
    __shared__ __half Bs_hi[128 * PADK];

    int tid = threadIdx.x;
    int wid = tid >> 5, lane = tid & 31;
    int wm = wid & 3, wn = wid >> 2;       // 4 warps over M(32 each), 2 over N(64 each)
    int g = lane >> 2, t = lane & 3;

    const float* Ab = A + (size_t)blockIdx.y * 128 * K;
    const float* Wb = W + (size_t)blockIdx.x * 128 * K;

    float acc[2][8][4];
#pragma unroll
    for (int mi = 0; mi < 2; mi++)
#pragma unroll
        for (int ni = 0; ni < 8; ni++)
#pragma unroll
            for (int r = 0; r < 4; r++) acc[mi][ni][r] = 0.0f;

    // per-thread staging: 4 float4 from A tile, 4 from W tile per 32-K chunk
    int srow[4], sc4[4];
#pragma unroll
    for (int i = 0; i < 4; i++) {
        int idx = tid + i * 256;           // 0..1023
        srow[i] = idx >> 3;
        sc4[i] = (idx & 7) * 4;
    }

    float4 av[4], bv[4];
#pragma unroll
    for (int i = 0; i < 4; i++) {
        av[i] = *(const float4*)(Ab + (size_t)srow[i] * K + sc4[i]);
        bv[i] = *(const float4*)(Wb + (size_t)srow[i] * K + sc4[i]);
    }

    for (int kt = 0; kt < K; kt += 32) {
        // split + store staged chunk to smem
#pragma unroll
        for (int i = 0; i < 4; i++) {
            float va[4] = {av[i].x, av[i].y, av[i].z, av[i].w};
            float vb[4] = {bv[i].x, bv[i].y, bv[i].z, bv[i].w};
            __half ah[4], al[4], bh[4];
#pragma unroll
            for (int j = 0; j < 4; j++) {
                ah[j] = __float2half_rn(va[j]);
                al[j] = __float2half_rn(va[j] - __half2float(ah[j]));
                bh[j] = __float2half_rn(vb[j]);
            }
            int off = srow[i] * PADK + sc4[i];
            *(uint2*)&As_hi[off] = make_uint2(pack_h2(ah[0], ah[1]), pack_h2(ah[2], ah[3]));
            *(uint2*)&As_lo[off] = make_uint2(pack_h2(al[0], al[1]), pack_h2(al[2], al[3]));
            *(uint2*)&Bs_hi[off] = make_uint2(pack_h2(bh[0], bh[1]), pack_h2(bh[2], bh[3]));
        }
        __syncthreads();

        // prefetch next chunk (LDGs in flight during compute)
        if (kt + 32 < K) {
#pragma unroll
            for (int i = 0; i < 4; i++) {
                av[i] = *(const float4*)(Ab + (size_t)srow[i] * K + kt + 32 + sc4[i]);
                bv[i] = *(const float4*)(Wb + (size_t)srow[i] * K + kt + 32 + sc4[i]);
            }
        }

#pragma unroll
        for (int k0 = 0; k0 < 32; k0 += 16) {
            unsigned ah[2][4], al[2][4];
#pragma unroll
            for (int mi = 0; mi < 2; mi++) {
                int rb = wm * 32 + mi * 16;
                int o00 = (rb + g) * PADK + k0 + 2 * t;
                int o10 = (rb + g + 8) * PADK + k0 + 2 * t;
                ah[mi][0] = *(const unsigned*)&As_hi[o00];
                ah[mi][1] = *(const unsigned*)&As_hi[o10];
                ah[mi][2] = *(const unsigned*)&As_hi[o00 + 8];
                ah[mi][3] = *(const unsigned*)&As_hi[o10 + 8];
                al[mi][0] = *(const unsigned*)&As_lo[o00];
                al[mi][1] = *(const unsigned*)&As_lo[o10];
                al[mi][2] = *(const unsigned*)&As_lo[o00 + 8];
                al[mi][3] = *(const unsigned*)&As_lo[o10 + 8];
            }
#pragma unroll
            for (int ni = 0; ni < 8; ni++) {
                int nb = wn * 64 + ni * 8;
                int ob = (nb + g) * PADK + k0 + 2 * t;
                unsigned bh[2];
                bh[0] = *(const unsigned*)&Bs_hi[ob];
                bh[1] = *(const unsigned*)&Bs_hi[ob + 8];
#pragma unroll
                for (int mi = 0; mi < 2; mi++) {
                    mma16816f(acc[mi][ni], ah[mi], bh);
                    mma16816f(acc[mi][ni], al[mi], bh);
                }
            }
        }
        __syncthreads();
    }

    // epilogue: bias + store (float2 per fragment row-pair)
#pragma unroll
    for (int mi = 0; mi < 2; mi++) {
#pragma unroll
        for (int ni = 0; ni < 8; ni++) {
            int col = blockIdx.x * 128 + wn * 64 + ni * 8 + 2 * t;
            float b0 = bias[col], b1 = bias[col + 1];
            size_t row0 = (size_t)blockIdx.y * 128 + wm * 32 + mi * 16 + g;
            *(float2*)(C + row0 * N + col) =
                make_float2(acc[mi][ni][0] + b0, acc[mi][ni][1] + b1);
            *(float2*)(C + (row0 + 8) * N + col) =
                make_float2(acc[mi][ni][2] + b0, acc[mi][ni][3] + b1);
        }
    }
}

// ---------------------------------------------------------------------------
// LayerNorm + 2D RoPE on Q, in place. One warp per (b, s, h) head-chunk.
// ---------------------------------------------------------------------------
__global__ void ln_rope_q(float* __restrict__ q,
                          const float* __restrict__ g, const float* __restrict__ bt)
{
    int gw = (blockIdx.x * blockDim.x + threadIdx.x) >> 5;
    int lane = threadIdx.x & 31;
    if (gw >= BB * S1 * NH) return;
    float2* p = (float2*)(q + (size_t)gw * HD);
    float2 v = p[lane];
    float sum = v.x + v.y;
    float sq = v.x * v.x + v.y * v.y;
#pragma unroll
    for (int o = 16; o; o >>= 1) {
        sum += __shfl_xor_sync(0xffffffffu, sum, o);
        sq  += __shfl_xor_sync(0xffffffffu, sq, o);
    }
    float mu = sum * (1.0f / HD);
    float var = sq * (1.0f / HD) - mu * mu;
    float rstd = rsqrtf(var + EPSF);
    float e  = (v.x - mu) * rstd * g[2 * lane]     + bt[2 * lane];
    float od = (v.y - mu) * rstd * g[2 * lane + 1] + bt[2 * lane + 1];

    int s = (gw / NH) & (S1 - 1);
    int hh = s >> 6, ww = s & 63;
    int t = lane >> 1;
    float inv = exp10f(-0.25f * (float)t);
    float ang = ((lane & 1) ? (float)ww : (float)hh) * inv;
    float n = rintf(ang * 0.15915494309189535f);
    ang -= n * 6.283185307179586f;
    float sn, cs;
    sincosf(ang, &sn, &cs);
    p[lane] = make_float2(e * cs - od * sn, e * sn + od * cs);
}

// LayerNorm on K, in place. One warp per (b, s2, h).
__global__ void ln_k(float* __restrict__ kv,
                     const float* __restrict__ g, const float* __restrict__ bt)
{
    int gw = (blockIdx.x * blockDim.x + threadIdx.x) >> 5;
    int lane = threadIdx.x & 31;
    if (gw >= BB * S2 * NH) return;
    int row = gw / NH, h = gw % NH;
    float2* p = (float2*)(kv + (size_t)row * KVD + h * HD);
    float2 v = p[lane];
    float sum = v.x + v.y;
    float sq = v.x * v.x + v.y * v.y;
#pragma unroll
    for (int o = 16; o; o >>= 1) {
        sum += __shfl_xor_sync(0xffffffffu, sum, o);
        sq  += __shfl_xor_sync(0xffffffffu, sq, o);
    }
    float mu = sum * (1.0f / HD);
    float var = sq * (1.0f / HD) - mu * mu;
    float rstd = rsqrtf(var + EPSF);
    float e  = (v.x - mu) * rstd * g[2 * lane]     + bt[2 * lane];
    float od = (v.y - mu) * rstd * g[2 * lane + 1] + bt[2 * lane + 1];
    p[lane] = make_float2(e, od);
}

// ---------------------------------------------------------------------------
// Attention (fp32 SIMT): one block = 128 query rows of one (b,h). S2=256 keys.
// ---------------------------------------------------------------------------
__global__ __launch_bounds__(256) void attention_kernel(
    const float* __restrict__ q, const float* __restrict__ kv,
    float* __restrict__ out)
{
    extern __shared__ float sm[];
    float* Qs = sm;
    float* Ks = sm + AR * HD;
    float* Ss = Ks + S2 * 65;
    int bh = blockIdx.y;
    int b = bh >> 4, h = bh & 15;
    int r0 = blockIdx.x * AR;
    int tid = threadIdx.x;

    for (int i = tid; i < AR * HD; i += 256) {
        int r = i >> 6, d = i & 63;
        Qs[i] = q[(((size_t)b * S1 + r0 + r) * NH + h) * HD + d];
    }
    for (int i = tid; i < S2 * HD; i += 256) {
        int k = i >> 6, d = i & 63;
        Ks[k * 65 + d] = kv[((size_t)b * S2 + k) * KVD + h * HD + d];
    }
    __syncthreads();

    float kreg[64];
#pragma unroll
    for (int d = 0; d < 64; d++) kreg[d] = Ks[tid * 65 + d];

    for (int r = 0; r < AR; r += 2) {
        const float* q0 = Qs + r * 64;
        const float* q1 = q0 + 64;
        float a0 = 0, a1 = 0, c0 = 0, c1 = 0;
#pragma unroll
        for (int d = 0; d < 64; d += 2) {
            a0 += q0[d] * kreg[d];     a1 += q0[d + 1] * kreg[d + 1];
            c0 += q1[d] * kreg[d];     c1 += q1[d + 1] * kreg[d + 1];
        }
        Ss[r * 256 + tid]       = (a0 + a1) * SCALEF;
        Ss[(r + 1) * 256 + tid] = (c0 + c1) * SCALEF;
    }
    __syncthreads();

    int wid = tid >> 5, lane = tid & 31;
    for (int r = wid; r < AR; r += 8) {
        float* srow = Ss + r * 256;
        float vals[8];
        float m = -1e30f;
#pragma unroll
        for (int i = 0; i < 8; i++) { vals[i] = srow[lane + 32 * i]; m = fmaxf(m, vals[i]); }
#pragma unroll
        for (int o = 16; o; o >>= 1) m = fmaxf(m, __shfl_xor_sync(0xffffffffu, m, o));
        float l = 0;
#pragma unroll
        for (int i = 0; i < 8; i++) { vals[i] = __expf(vals[i] - m); l += vals[i]; }
#pragma unroll
        for (int o = 16; o; o >>= 1) l += __shfl_xor_sync(0xffffffffu, l, o);
        float rl = 1.0f / l;
#pragma unroll
        for (int i = 0; i < 8; i++) srow[lane + 32 * i] = vals[i] * rl;
    }
    __syncthreads();

    for (int i = tid; i < S2 * HD; i += 256) {
        int k = i >> 6, d = i & 63;
        Ks[k * 65 + d] = kv[((size_t)b * S2 + k) * KVD + QD + h * HD + d];
    }
    __syncthreads();

    int d0 = lane, d1 = lane + 32;
    for (int i = 0; i < 16; i++) {
        int r = wid + 8 * i;
        const float* srow = Ss + r * 256;
        float acc0 = 0, acc1 = 0;
#pragma unroll 8
        for (int k = 0; k < 256; k++) {
            float pv = srow[k];
            acc0 += pv * Ks[k * 65 + d0];
            acc1 += pv * Ks[k * 65 + d1];
        }
        size_t ob = (((size_t)b * S1 + r0 + r) * NH + h) * HD;
        out[ob + d0] = acc0;
        out[ob + d1] = acc1;
    }
}

// ---------------------------------------------------------------------------
extern "C" void kernel_launch(void* const* d_in, const int* in_sizes, int n_in,
                              void* d_out, int out_size)
{
    (void)in_sizes; (void)n_in; (void)out_size;
    const float* x   = (const float*)d_in[0];
    const float* y   = (const float*)d_in[1];
    const float* wq  = (const float*)d_in[2];
    const float* bq  = (const float*)d_in[3];
    const float* wkv = (const float*)d_in[4];
    const float* bkv = (const float*)d_in[5];
    const float* wo  = (const float*)d_in[6];
    const float* bo  = (const float*)d_in[7];
    const float* qng = (const float*)d_in[8];
    const float* qnb = (const float*)d_in[9];
    const float* kng = (const float*)d_in[10];
    const float* knb = (const float*)d_in[11];
    float* out = (float*)d_out;

    float *qbuf, *kvbuf, *abuf;
    cudaGetSymbolAddress((void**)&qbuf, g_q);
    cudaGetSymbolAddress((void**)&kvbuf, g_kv);
    cudaGetSymbolAddress((void**)&abuf, g_att);

    // 1) Q = x @ wq^T + bq
    gemm_bias_tc<<<dim3(QD / 128, (BB * S1) / 128), 256>>>(x, wq, bq, qbuf, BB * S1, QD, QD);
    // 2) KV = y @ wkv^T + bkv
    gemm_bias_tc<<<dim3(KVD / 128, (BB * S2) / 128), 256>>>(y, wkv, bkv, kvbuf, BB * S2, KVD, KVD);
    // 3) LN + RoPE on Q
    ln_rope_q<<<(BB * S1 * NH) / 4, 128>>>(qbuf, qng, qnb);
    // 4) LN on K
    ln_k<<<(BB * S2 * NH) / 4, 128>>>(kvbuf, kng, knb);
    // 5) attention
    {
        size_t smem = (size_t)(AR * HD + S2 * 65 + AR * S2) * sizeof(float);
        cudaFuncSetAttribute(attention_kernel,
                             cudaFuncAttributeMaxDynamicSharedMemorySize, (int)smem);
        attention_kernel<<<dim3(S1 / AR, BB * NH), 256, smem>>>(qbuf, kvbuf, abuf);
    }
    // 6) out = att @ wo^T + bo
    gemm_bias_tc<<<dim3(QD / 128, (BB * S1) / 128), 256>>>(abuf, wo, bo, out, BB * S1, QD, QD);
}

// round 11
// speedup vs baseline: 1.8365x; 1.0938x over previous
#include <cuda_runtime.h>
#include <cuda_fp16.h>
#include <math.h>

#define BB 8
#define S1 4096
#define S2 256
#define NH 16
#define HD 64
#define QD 1024
#define KVD 2048
#define EPSF 1e-6f
#define SCALEF 0.125f
#define AR 128

// Scratch (device globals — no allocation allowed)
__device__ float g_q[(size_t)BB * S1 * QD];
__device__ float g_kv[(size_t)BB * S2 * KVD];
__device__ float g_att[(size_t)BB * S1 * QD];

// ---------------------------------------------------------------------------
// Single-pass fp16 tensor-core GEMM:  C = A @ W^T + bias
// A:(M,K) fp32 row-major, W:(N,K) fp32 row-major, C:(M,N) fp32.
// Both operands rounded to fp16 (rel err ~2^-11 each, incoherent over K).
// Tile 128x128, BK=32, 256 threads (8 warps: 4 over M x 2 over N),
// warp tile 32x64 -> 2x8 m16n8k16 fragments. Register prefetch of next chunk.
// ---------------------------------------------------------------------------
#define PADK 40  // 32 + 8 halves padding: conflict-free fragment loads

__device__ __forceinline__ void mma16816f(float* c, const unsigned* a, const unsigned* b)
{
    asm volatile(
        "mma.sync.aligned.m16n8k16.row.col.f32.f16.f16.f32 "
        "{%0,%1,%2,%3}, {%4,%5,%6,%7}, {%8,%9}, {%0,%1,%2,%3};"
        : "+f"(c[0]), "+f"(c[1]), "+f"(c[2]), "+f"(c[3])
        : "r"(a[0]), "r"(a[1]), "r"(a[2]), "r"(a[3]), "r"(b[0]), "r"(b[1]));
}

__device__ __forceinline__ unsigned pack_h2(__half lo, __half hi)
{
    return (unsigned)__half_as_ushort(lo) | ((unsigned)__half_as_ushort(hi) << 16);
}

__global__ __launch_bounds__(256) void gemm_bias_tc(
    const float* __restrict__ A, const float* __restrict__ W,
    const float* __restrict__ bias, float* __restrict__ C,
    int M, int N, int K)
{
    __shared__ __half As_hi[128 * PADK];
    __shared__ __half Bs_hi[128 * PADK];

    int tid = threadIdx.x;
    int wid = tid >> 5, lane = tid & 31;
    int wm = wid & 3, wn = wid >> 2;       // 4 warps over M(32 each), 2 over N(64 each)
    int g = lane >> 2, t = lane & 3;

    const float* Ab = A + (size_t)blockIdx.y * 128 * K;
    const float* Wb = W + (size_t)blockIdx.x * 128 * K;

    float acc[2][8][4];
#pragma unroll
    for (int mi = 0; mi < 2; mi++)
#pragma unroll
        for (int ni = 0; ni < 8; ni++)
#pragma unroll
            for (int r = 0; r < 4; r++) acc[mi][ni][r] = 0.0f;

    // per-thread staging: 4 float4 from A tile, 4 from W tile per 32-K chunk
    int srow[4], sc4[4];
#pragma unroll
    for (int i = 0; i < 4; i++) {
        int idx = tid + i * 256;           // 0..1023
        srow[i] = idx >> 3;
        sc4[i] = (idx & 7) * 4;
    }

    float4 av[4], bv[4];
#pragma unroll
    for (int i = 0; i < 4; i++) {
        av[i] = *(const float4*)(Ab + (size_t)srow[i] * K + sc4[i]);
        bv[i] = *(const float4*)(Wb + (size_t)srow[i] * K + sc4[i]);
    }

    for (int kt = 0; kt < K; kt += 32) {
        // convert + store staged chunk to smem
#pragma unroll
        for (int i = 0; i < 4; i++) {
            float va[4] = {av[i].x, av[i].y, av[i].z, av[i].w};
            float vb[4] = {bv[i].x, bv[i].y, bv[i].z, bv[i].w};
            __half ah[4], bh[4];
#pragma unroll
            for (int j = 0; j < 4; j++) {
                ah[j] = __float2half_rn(va[j]);
                bh[j] = __float2half_rn(vb[j]);
            }
            int off = srow[i] * PADK + sc4[i];
            *(uint2*)&As_hi[off] = make_uint2(pack_h2(ah[0], ah[1]), pack_h2(ah[2], ah[3]));
            *(uint2*)&Bs_hi[off] = make_uint2(pack_h2(bh[0], bh[1]), pack_h2(bh[2], bh[3]));
        }
        __syncthreads();

        // prefetch next chunk (LDGs in flight during compute)
        if (kt + 32 < K) {
#pragma unroll
            for (int i = 0; i < 4; i++) {
                av[i] = *(const float4*)(Ab + (size_t)srow[i] * K + kt + 32 + sc4[i]);
                bv[i] = *(const float4*)(Wb + (size_t)srow[i] * K + kt + 32 + sc4[i]);
            }
        }

#pragma unroll
        for (int k0 = 0; k0 < 32; k0 += 16) {
            unsigned ah[2][4];
#pragma unroll
            for (int mi = 0; mi < 2; mi++) {
                int rb = wm * 32 + mi * 16;
                int o00 = (rb + g) * PADK + k0 + 2 * t;
                int o10 = (rb + g + 8) * PADK + k0 + 2 * t;
                ah[mi][0] = *(const unsigned*)&As_hi[o00];
                ah[mi][1] = *(const unsigned*)&As_hi[o10];
                ah[mi][2] = *(const unsigned*)&As_hi[o00 + 8];
                ah[mi][3] = *(const unsigned*)&As_hi[o10 + 8];
            }
#pragma unroll
            for (int ni = 0; ni < 8; ni++) {
                int nb = wn * 64 + ni * 8;
                int ob = (nb + g) * PADK + k0 + 2 * t;
                unsigned bh[2];
                bh[0] = *(const unsigned*)&Bs_hi[ob];
                bh[1] = *(const unsigned*)&Bs_hi[ob + 8];
#pragma unroll
                for (int mi = 0; mi < 2; mi++) {
                    mma16816f(acc[mi][ni], ah[mi], bh);
                }
            }
        }
        __syncthreads();
    }

    // epilogue: bias + store (float2 per fragment row-pair)
#pragma unroll
    for (int mi = 0; mi < 2; mi++) {
#pragma unroll
        for (int ni = 0; ni < 8; ni++) {
            int col = blockIdx.x * 128 + wn * 64 + ni * 8 + 2 * t;
            float b0 = bias[col], b1 = bias[col + 1];
            size_t row0 = (size_t)blockIdx.y * 128 + wm * 32 + mi * 16 + g;
            *(float2*)(C + row0 * N + col) =
                make_float2(acc[mi][ni][0] + b0, acc[mi][ni][1] + b1);
            *(float2*)(C + (row0 + 8) * N + col) =
                make_float2(acc[mi][ni][2] + b0, acc[mi][ni][3] + b1);
        }
    }
}

// ---------------------------------------------------------------------------
// LayerNorm + 2D RoPE on Q, in place. One warp per (b, s, h) head-chunk.
// ---------------------------------------------------------------------------
__global__ void ln_rope_q(float* __restrict__ q,
                          const float* __restrict__ g, const float* __restrict__ bt)
{
    int gw = (blockIdx.x * blockDim.x + threadIdx.x) >> 5;
    int lane = threadIdx.x & 31;
    if (gw >= BB * S1 * NH) return;
    float2* p = (float2*)(q + (size_t)gw * HD);
    float2 v = p[lane];
    float sum = v.x + v.y;
    float sq = v.x * v.x + v.y * v.y;
#pragma unroll
    for (int o = 16; o; o >>= 1) {
        sum += __shfl_xor_sync(0xffffffffu, sum, o);
        sq  += __shfl_xor_sync(0xffffffffu, sq, o);
    }
    float mu = sum * (1.0f / HD);
    float var = sq * (1.0f / HD) - mu * mu;
    float rstd = rsqrtf(var + EPSF);
    float e  = (v.x - mu) * rstd * g[2 * lane]     + bt[2 * lane];
    float od = (v.y - mu) * rstd * g[2 * lane + 1] + bt[2 * lane + 1];

    int s = (gw / NH) & (S1 - 1);
    int hh = s >> 6, ww = s & 63;
    int t = lane >> 1;
    float inv = exp10f(-0.25f * (float)t);
    float ang = ((lane & 1) ? (float)ww : (float)hh) * inv;
    float n = rintf(ang * 0.15915494309189535f);
    ang -= n * 6.283185307179586f;
    float sn, cs;
    sincosf(ang, &sn, &cs);
    p[lane] = make_float2(e * cs - od * sn, e * sn + od * cs);
}

// LayerNorm on K, in place. One warp per (b, s2, h).
__global__ void ln_k(float* __restrict__ kv,
                     const float* __restrict__ g, const float* __restrict__ bt)
{
    int gw = (blockIdx.x * blockDim.x + threadIdx.x) >> 5;
    int lane = threadIdx.x & 31;
    if (gw >= BB * S2 * NH) return;
    int row = gw / NH, h = gw % NH;
    float2* p = (float2*)(kv + (size_t)row * KVD + h * HD);
    float2 v = p[lane];
    float sum = v.x + v.y;
    float sq = v.x * v.x + v.y * v.y;
#pragma unroll
    for (int o = 16; o; o >>= 1) {
        sum += __shfl_xor_sync(0xffffffffu, sum, o);
        sq  += __shfl_xor_sync(0xffffffffu, sq, o);
    }
    float mu = sum * (1.0f / HD);
    float var = sq * (1.0f / HD) - mu * mu;
    float rstd = rsqrtf(var + EPSF);
    float e  = (v.x - mu) * rstd * g[2 * lane]     + bt[2 * lane];
    float od = (v.y - mu) * rstd * g[2 * lane + 1] + bt[2 * lane + 1];
    p[lane] = make_float2(e, od);
}

// ---------------------------------------------------------------------------
// Attention (fp32 SIMT): one block = 128 query rows of one (b,h). S2=256 keys.
// ---------------------------------------------------------------------------
__global__ __launch_bounds__(256) void attention_kernel(
    const float* __restrict__ q, const float* __restrict__ kv,
    float* __restrict__ out)
{
    extern __shared__ float sm[];
    float* Qs = sm;
    float* Ks = sm + AR * HD;
    float* Ss = Ks + S2 * 65;
    int bh = blockIdx.y;
    int b = bh >> 4, h = bh & 15;
    int r0 = blockIdx.x * AR;
    int tid = threadIdx.x;

    for (int i = tid; i < AR * HD; i += 256) {
        int r = i >> 6, d = i & 63;
        Qs[i] = q[(((size_t)b * S1 + r0 + r) * NH + h) * HD + d];
    }
    for (int i = tid; i < S2 * HD; i += 256) {
        int k = i >> 6, d = i & 63;
        Ks[k * 65 + d] = kv[((size_t)b * S2 + k) * KVD + h * HD + d];
    }
    __syncthreads();

    float kreg[64];
#pragma unroll
    for (int d = 0; d < 64; d++) kreg[d] = Ks[tid * 65 + d];

    for (int r = 0; r < AR; r += 2) {
        const float* q0 = Qs + r * 64;
        const float* q1 = q0 + 64;
        float a0 = 0, a1 = 0, c0 = 0, c1 = 0;
#pragma unroll
        for (int d = 0; d < 64; d += 2) {
            a0 += q0[d] * kreg[d];     a1 += q0[d + 1] * kreg[d + 1];
            c0 += q1[d] * kreg[d];     c1 += q1[d + 1] * kreg[d + 1];
        }
        Ss[r * 256 + tid]       = (a0 + a1) * SCALEF;
        Ss[(r + 1) * 256 + tid] = (c0 + c1) * SCALEF;
    }
    __syncthreads();

    int wid = tid >> 5, lane = tid & 31;
    for (int r = wid; r < AR; r += 8) {
        float* srow = Ss + r * 256;
        float vals[8];
        float m = -1e30f;
#pragma unroll
        for (int i = 0; i < 8; i++) { vals[i] = srow[lane + 32 * i]; m = fmaxf(m, vals[i]); }
#pragma unroll
        for (int o = 16; o; o >>= 1) m = fmaxf(m, __shfl_xor_sync(0xffffffffu, m, o));
        float l = 0;
#pragma unroll
        for (int i = 0; i < 8; i++) { vals[i] = __expf(vals[i] - m); l += vals[i]; }
#pragma unroll
        for (int o = 16; o; o >>= 1) l += __shfl_xor_sync(0xffffffffu, l, o);
        float rl = 1.0f / l;
#pragma unroll
        for (int i = 0; i < 8; i++) srow[lane + 32 * i] = vals[i] * rl;
    }
    __syncthreads();

    for (int i = tid; i < S2 * HD; i += 256) {
        int k = i >> 6, d = i & 63;
        Ks[k * 65 + d] = kv[((size_t)b * S2 + k) * KVD + QD + h * HD + d];
    }
    __syncthreads();

    int d0 = lane, d1 = lane + 32;
    for (int i = 0; i < 16; i++) {
        int r = wid + 8 * i;
        const float* srow = Ss + r * 256;
        float acc0 = 0, acc1 = 0;
#pragma unroll 8
        for (int k = 0; k < 256; k++) {
            float pv = srow[k];
            acc0 += pv * Ks[k * 65 + d0];
            acc1 += pv * Ks[k * 65 + d1];
        }
        size_t ob = (((size_t)b * S1 + r0 + r) * NH + h) * HD;
        out[ob + d0] = acc0;
        out[ob + d1] = acc1;
    }
}

// ---------------------------------------------------------------------------
extern "C" void kernel_launch(void* const* d_in, const int* in_sizes, int n_in,
                              void* d_out, int out_size)
{
    (void)in_sizes; (void)n_in; (void)out_size;
    const float* x   = (const float*)d_in[0];
    const float* y   = (const float*)d_in[1];
    const float* wq  = (const float*)d_in[2];
    const float* bq  = (const float*)d_in[3];
    const float* wkv = (const float*)d_in[4];
    const float* bkv = (const float*)d_in[5];
    const float* wo  = (const float*)d_in[6];
    const float* bo  = (const float*)d_in[7];
    const float* qng = (const float*)d_in[8];
    const float* qnb = (const float*)d_in[9];
    const float* kng = (const float*)d_in[10];
    const float* knb = (const float*)d_in[11];
    float* out = (float*)d_out;

    float *qbuf, *kvbuf, *abuf;
    cudaGetSymbolAddress((void**)&qbuf, g_q);
    cudaGetSymbolAddress((void**)&kvbuf, g_kv);
    cudaGetSymbolAddress((void**)&abuf, g_att);

    // 1) Q = x @ wq^T + bq
    gemm_bias_tc<<<dim3(QD / 128, (BB * S1) / 128), 256>>>(x, wq, bq, qbuf, BB * S1, QD, QD);
    // 2) KV = y @ wkv^T + bkv
    gemm_bias_tc<<<dim3(KVD / 128, (BB * S2) / 128), 256>>>(y, wkv, bkv, kvbuf, BB * S2, KVD, KVD);
    // 3) LN + RoPE on Q
    ln_rope_q<<<(BB * S1 * NH) / 4, 128>>>(qbuf, qng, qnb);
    // 4) LN on K
    ln_k<<<(BB * S2 * NH) / 4, 128>>>(kvbuf, kng, knb);
    // 5) attention
    {
        size_t smem = (size_t)(AR * HD + S2 * 65 + AR * S2) * sizeof(float);
        cudaFuncSetAttribute(attention_kernel,
                             cudaFuncAttributeMaxDynamicSharedMemorySize, (int)smem);
        attention_kernel<<<dim3(S1 / AR, BB * NH), 256, smem>>>(qbuf, kvbuf, abuf);
    }
    // 6) out = att @ wo^T + bo
    gemm_bias_tc<<<dim3(QD / 128, (BB * S1) / 128), 256>>>(abuf, wo, bo, out, BB * S1, QD, QD);
}

// round 13
// speedup vs baseline: 2.0473x; 1.1148x over previous
#include <cuda_runtime.h>
#include <cuda_fp16.h>
#include <math.h>

#define BB 8
#define S1 4096
#define S2 256
#define NH 16
#define HD 64
#define QD 1024
#define KVD 2048
#define EPSF 1e-6f
#define SCALEF 0.125f
#define AR 128

#define PADK 40                 // halfs per smem row (32 + 8 pad)
#define OPH (128 * PADK)        // 5120 halfs per operand tile (10240 B)
#define STH (2 * OPH)           // halfs per stage (A + W)
#define NST 3
#define GSM (NST * STH * 2)     // 61440 bytes dynamic smem

// ---------------- scratch (device globals; no allocation allowed) ----------
__device__ float g_q[(size_t)BB * S1 * QD];
__device__ float g_kv[(size_t)BB * S2 * KVD];
__device__ __half g_xh[(size_t)BB * S1 * QD];
__device__ __half g_yh[(size_t)BB * S2 * KVD];
__device__ __half g_wqh[(size_t)QD * QD];
__device__ __half g_wkvh[(size_t)2 * QD * KVD];
__device__ __half g_woh[(size_t)QD * QD];
__device__ __half g_atth[(size_t)BB * S1 * QD];

// ---------------------------------------------------------------------------
__device__ __forceinline__ void mma16816f(float* c, const unsigned* a, const unsigned* b)
{
    asm volatile(
        "mma.sync.aligned.m16n8k16.row.col.f32.f16.f16.f32 "
        "{%0,%1,%2,%3}, {%4,%5,%6,%7}, {%8,%9}, {%0,%1,%2,%3};"
        : "+f"(c[0]), "+f"(c[1]), "+f"(c[2]), "+f"(c[3])
        : "r"(a[0]), "r"(a[1]), "r"(a[2]), "r"(a[3]), "r"(b[0]), "r"(b[1]));
}

__device__ __forceinline__ unsigned pack_h2(__half lo, __half hi)
{
    return (unsigned)__half_as_ushort(lo) | ((unsigned)__half_as_ushort(hi) << 16);
}

__device__ __forceinline__ void cp16cg(__half* dst, const __half* src)
{
    unsigned d = (unsigned)__cvta_generic_to_shared(dst);
    asm volatile("cp.async.cg.shared.global [%0], [%1], 16;" :: "r"(d), "l"(src));
}
__device__ __forceinline__ void cp_commit() { asm volatile("cp.async.commit_group;" ::: "memory"); }
__device__ __forceinline__ void cp_wait1()  { asm volatile("cp.async.wait_group 1;" ::: "memory"); }

// ---------------------------------------------------------------------------
// fp32 -> fp16 conversion pass
// ---------------------------------------------------------------------------
__global__ void to_half(const float* __restrict__ in, __half* __restrict__ out, int n4)
{
    int i = blockIdx.x * blockDim.x + threadIdx.x;
    if (i >= n4) return;
    float4 v = ((const float4*)in)[i];
    ((uint2*)out)[i] = make_uint2(
        pack_h2(__float2half_rn(v.x), __float2half_rn(v.y)),
        pack_h2(__float2half_rn(v.z), __float2half_rn(v.w)));
}

// ---------------------------------------------------------------------------
// fp16 tensor-core GEMM: C = A @ W^T + bias.  A:(M,K) W:(N,K) fp16 row-major.
// Tile 128x128, BK=32, 3-stage cp.async pipeline, 256 threads
// (8 warps: 4 over M x 2 over N), warp tile 32x64 -> 2x8 m16n8k16 fragments.
// ---------------------------------------------------------------------------
__device__ __forceinline__ void issue_stage(
    __half* sh, int s, const __half* Ab, const __half* Wb, int K, int kc, int tid)
{
    __half* base = sh + s * STH;
#pragma unroll
    for (int i = 0; i < 2; i++) {
        int c = tid + i * 256;          // 0..511
        int row = c >> 2;
        int seg = c & 3;                // 4 x 16B segments per 32-half row
        int soff = row * PADK + seg * 8;
        size_t goff = (size_t)row * K + kc * 32 + seg * 8;
        cp16cg(base + soff, Ab + goff);
        cp16cg(base + OPH + soff, Wb + goff);
    }
}

__global__ __launch_bounds__(256) void gemm_h(
    const __half* __restrict__ A, const __half* __restrict__ W,
    const float* __restrict__ bias, float* __restrict__ C,
    int M, int N, int K)
{
    extern __shared__ __half sh[];

    int tid = threadIdx.x;
    int wid = tid >> 5, lane = tid & 31;
    int wm = wid & 3, wn = wid >> 2;
    int g = lane >> 2, t = lane & 3;

    const __half* Ab = A + (size_t)blockIdx.y * 128 * K;
    const __half* Wb = W + (size_t)blockIdx.x * 128 * K;

    float acc[2][8][4];
#pragma unroll
    for (int mi = 0; mi < 2; mi++)
#pragma unroll
        for (int ni = 0; ni < 8; ni++)
#pragma unroll
            for (int r = 0; r < 4; r++) acc[mi][ni][r] = 0.0f;

    int nch = K >> 5;

    issue_stage(sh, 0, Ab, Wb, K, 0, tid);
    cp_commit();
    issue_stage(sh, 1, Ab, Wb, K, 1, tid);
    cp_commit();

    int cur = 0;
    for (int ki = 0; ki < nch; ki++) {
        cp_wait1();
        __syncthreads();   // chunk ki visible to all; all warps done with stage being overwritten

        int nk = ki + 2;
        if (nk < nch) {
            issue_stage(sh, (cur + 2) % NST, Ab, Wb, K, nk, tid);
        }
        cp_commit();

        const __half* As = sh + cur * STH;
        const __half* Bs = As + OPH;

#pragma unroll
        for (int k0 = 0; k0 < 32; k0 += 16) {
            unsigned ah[2][4];
#pragma unroll
            for (int mi = 0; mi < 2; mi++) {
                int rb = wm * 32 + mi * 16;
                int o00 = (rb + g) * PADK + k0 + 2 * t;
                int o10 = (rb + g + 8) * PADK + k0 + 2 * t;
                ah[mi][0] = *(const unsigned*)&As[o00];
                ah[mi][1] = *(const unsigned*)&As[o10];
                ah[mi][2] = *(const unsigned*)&As[o00 + 8];
                ah[mi][3] = *(const unsigned*)&As[o10 + 8];
            }
#pragma unroll
            for (int ni = 0; ni < 8; ni++) {
                int nb = wn * 64 + ni * 8;
                int ob = (nb + g) * PADK + k0 + 2 * t;
                unsigned bh[2];
                bh[0] = *(const unsigned*)&Bs[ob];
                bh[1] = *(const unsigned*)&Bs[ob + 8];
#pragma unroll
                for (int mi = 0; mi < 2; mi++) {
                    mma16816f(acc[mi][ni], ah[mi], bh);
                }
            }
        }

        cur = (cur + 1) % NST;
    }

    // epilogue: bias + fp32 store
#pragma unroll
    for (int mi = 0; mi < 2; mi++) {
#pragma unroll
        for (int ni = 0; ni < 8; ni++) {
            int col = blockIdx.x * 128 + wn * 64 + ni * 8 + 2 * t;
            float b0 = bias[col], b1 = bias[col + 1];
            size_t row0 = (size_t)blockIdx.y * 128 + wm * 32 + mi * 16 + g;
            *(float2*)(C + row0 * N + col) =
                make_float2(acc[mi][ni][0] + b0, acc[mi][ni][1] + b1);
            *(float2*)(C + (row0 + 8) * N + col) =
                make_float2(acc[mi][ni][2] + b0, acc[mi][ni][3] + b1);
        }
    }
}

// ---------------------------------------------------------------------------
// LayerNorm + 2D RoPE on Q, in place. One warp per (b, s, h).
// ---------------------------------------------------------------------------
__global__ void ln_rope_q(float* __restrict__ q,
                          const float* __restrict__ g, const float* __restrict__ bt)
{
    int gw = (blockIdx.x * blockDim.x + threadIdx.x) >> 5;
    int lane = threadIdx.x & 31;
    if (gw >= BB * S1 * NH) return;
    float2* p = (float2*)(q + (size_t)gw * HD);
    float2 v = p[lane];
    float sum = v.x + v.y;
    float sq = v.x * v.x + v.y * v.y;
#pragma unroll
    for (int o = 16; o; o >>= 1) {
        sum += __shfl_xor_sync(0xffffffffu, sum, o);
        sq  += __shfl_xor_sync(0xffffffffu, sq, o);
    }
    float mu = sum * (1.0f / HD);
    float var = sq * (1.0f / HD) - mu * mu;
    float rstd = rsqrtf(var + EPSF);
    float e  = (v.x - mu) * rstd * g[2 * lane]     + bt[2 * lane];
    float od = (v.y - mu) * rstd * g[2 * lane + 1] + bt[2 * lane + 1];

    int s = (gw / NH) & (S1 - 1);
    int hh = s >> 6, ww = s & 63;
    int t = lane >> 1;
    float inv = exp10f(-0.25f * (float)t);
    float ang = ((lane & 1) ? (float)ww : (float)hh) * inv;
    float n = rintf(ang * 0.15915494309189535f);
    ang -= n * 6.283185307179586f;
    float sn, cs;
    sincosf(ang, &sn, &cs);
    p[lane] = make_float2(e * cs - od * sn, e * sn + od * cs);
}

// LayerNorm on K, in place. One warp per (b, s2, h).
__global__ void ln_k(float* __restrict__ kv,
                     const float* __restrict__ g, const float* __restrict__ bt)
{
    int gw = (blockIdx.x * blockDim.x + threadIdx.x) >> 5;
    int lane = threadIdx.x & 31;
    if (gw >= BB * S2 * NH) return;
    int row = gw / NH, h = gw % NH;
    float2* p = (float2*)(kv + (size_t)row * KVD + h * HD);
    float2 v = p[lane];
    float sum = v.x + v.y;
    float sq = v.x * v.x + v.y * v.y;
#pragma unroll
    for (int o = 16; o; o >>= 1) {
        sum += __shfl_xor_sync(0xffffffffu, sum, o);
        sq  += __shfl_xor_sync(0xffffffffu, sq, o);
    }
    float mu = sum * (1.0f / HD);
    float var = sq * (1.0f / HD) - mu * mu;
    float rstd = rsqrtf(var + EPSF);
    float e  = (v.x - mu) * rstd * g[2 * lane]     + bt[2 * lane];
    float od = (v.y - mu) * rstd * g[2 * lane + 1] + bt[2 * lane + 1];
    p[lane] = make_float2(e, od);
}

// ---------------------------------------------------------------------------
// Attention (fp32 SIMT); output written as fp16 for GEMM3.
// ---------------------------------------------------------------------------
__global__ __launch_bounds__(256) void attention_kernel(
    const float* __restrict__ q, const float* __restrict__ kv,
    __half* __restrict__ oh)
{
    extern __shared__ float sm[];
    float* Qs = sm;
    float* Ks = sm + AR * HD;
    float* Ss = Ks + S2 * 65;
    int bh = blockIdx.y;
    int b = bh >> 4, h = bh & 15;
    int r0 = blockIdx.x * AR;
    int tid = threadIdx.x;

    for (int i = tid; i < AR * HD; i += 256) {
        int r = i >> 6, d = i & 63;
        Qs[i] = q[(((size_t)b * S1 + r0 + r) * NH + h) * HD + d];
    }
    for (int i = tid; i < S2 * HD; i += 256) {
        int k = i >> 6, d = i & 63;
        Ks[k * 65 + d] = kv[((size_t)b * S2 + k) * KVD + h * HD + d];
    }
    __syncthreads();

    float kreg[64];
#pragma unroll
    for (int d = 0; d < 64; d++) kreg[d] = Ks[tid * 65 + d];

    for (int r = 0; r < AR; r += 2) {
        const float* q0 = Qs + r * 64;
        const float* q1 = q0 + 64;
        float a0 = 0, a1 = 0, c0 = 0, c1 = 0;
#pragma unroll
        for (int d = 0; d < 64; d += 2) {
            a0 += q0[d] * kreg[d];     a1 += q0[d + 1] * kreg[d + 1];
            c0 += q1[d] * kreg[d];     c1 += q1[d + 1] * kreg[d + 1];
        }
        Ss[r * 256 + tid]       = (a0 + a1) * SCALEF;
        Ss[(r + 1) * 256 + tid] = (c0 + c1) * SCALEF;
    }
    __syncthreads();

    int wid = tid >> 5, lane = tid & 31;
    for (int r = wid; r < AR; r += 8) {
        float* srow = Ss + r * 256;
        float vals[8];
        float m = -1e30f;
#pragma unroll
        for (int i = 0; i < 8; i++) { vals[i] = srow[lane + 32 * i]; m = fmaxf(m, vals[i]); }
#pragma unroll
        for (int o = 16; o; o >>= 1) m = fmaxf(m, __shfl_xor_sync(0xffffffffu, m, o));
        float l = 0;
#pragma unroll
        for (int i = 0; i < 8; i++) { vals[i] = __expf(vals[i] - m); l += vals[i]; }
#pragma unroll
        for (int o = 16; o; o >>= 1) l += __shfl_xor_sync(0xffffffffu, l, o);
        float rl = 1.0f / l;
#pragma unroll
        for (int i = 0; i < 8; i++) srow[lane + 32 * i] = vals[i] * rl;
    }
    __syncthreads();

    for (int i = tid; i < S2 * HD; i += 256) {
        int k = i >> 6, d = i & 63;
        Ks[k * 65 + d] = kv[((size_t)b * S2 + k) * KVD + QD + h * HD + d];
    }
    __syncthreads();

    int d0 = lane, d1 = lane + 32;
    for (int i = 0; i < 16; i++) {
        int r = wid + 8 * i;
        const float* srow = Ss + r * 256;
        float acc0 = 0, acc1 = 0;
#pragma unroll 8
        for (int k = 0; k < 256; k++) {
            float pv = srow[k];
            acc0 += pv * Ks[k * 65 + d0];
            acc1 += pv * Ks[k * 65 + d1];
        }
        size_t ob = (((size_t)b * S1 + r0 + r) * NH + h) * HD;
        oh[ob + d0] = __float2half_rn(acc0);
        oh[ob + d1] = __float2half_rn(acc1);
    }
}

// ---------------------------------------------------------------------------
extern "C" void kernel_launch(void* const* d_in, const int* in_sizes, int n_in,
                              void* d_out, int out_size)
{
    (void)in_sizes; (void)n_in; (void)out_size;
    const float* x   = (const float*)d_in[0];
    const float* y   = (const float*)d_in[1];
    const float* wq  = (const float*)d_in[2];
    const float* bq  = (const float*)d_in[3];
    const float* wkv = (const float*)d_in[4];
    const float* bkv = (const float*)d_in[5];
    const float* wo  = (const float*)d_in[6];
    const float* bo  = (const float*)d_in[7];
    const float* qng = (const float*)d_in[8];
    const float* qnb = (const float*)d_in[9];
    const float* kng = (const float*)d_in[10];
    const float* knb = (const float*)d_in[11];
    float* out = (float*)d_out;

    float* qbuf;
    float* kvbuf;
    __half* xh;
    __half* yh;
    __half* wqh;
    __half* wkvh;
    __half* woh;
    __half* atth;
    cudaGetSymbolAddress((void**)&qbuf, g_q);
    cudaGetSymbolAddress((void**)&kvbuf, g_kv);
    cudaGetSymbolAddress((void**)&xh, g_xh);
    cudaGetSymbolAddress((void**)&yh, g_yh);
    cudaGetSymbolAddress((void**)&wqh, g_wqh);
    cudaGetSymbolAddress((void**)&wkvh, g_wkvh);
    cudaGetSymbolAddress((void**)&woh, g_woh);
    cudaGetSymbolAddress((void**)&atth, g_atth);

    // 0) convert inputs to fp16
    int n;
    n = BB * S1 * QD / 4;
    to_half<<<(n + 255) / 256, 256>>>(x, xh, n);
    n = BB * S2 * KVD / 4;
    to_half<<<(n + 255) / 256, 256>>>(y, yh, n);
    n = QD * QD / 4;
    to_half<<<(n + 255) / 256, 256>>>(wq, wqh, n);
    n = 2 * QD * KVD / 4;
    to_half<<<(n + 255) / 256, 256>>>(wkv, wkvh, n);
    n = QD * QD / 4;
    to_half<<<(n + 255) / 256, 256>>>(wo, woh, n);

    cudaFuncSetAttribute(gemm_h, cudaFuncAttributeMaxDynamicSharedMemorySize, GSM);

    // 1) Q = x @ wq^T + bq
    gemm_h<<<dim3(QD / 128, (BB * S1) / 128), 256, GSM>>>(xh, wqh, bq, qbuf, BB * S1, QD, QD);
    // 2) KV = y @ wkv^T + bkv
    gemm_h<<<dim3(KVD / 128, (BB * S2) / 128), 256, GSM>>>(yh, wkvh, bkv, kvbuf, BB * S2, KVD, KVD);
    // 3) LN + RoPE on Q
    ln_rope_q<<<(BB * S1 * NH) / 4, 128>>>(qbuf, qng, qnb);
    // 4) LN on K
    ln_k<<<(BB * S2 * NH) / 4, 128>>>(kvbuf, kng, knb);
    // 5) attention (writes fp16)
    size_t asmem = (size_t)(AR * HD + S2 * 65 + AR * S2) * sizeof(float);
    cudaFuncSetAttribute(attention_kernel,
                         cudaFuncAttributeMaxDynamicSharedMemorySize, (int)asmem);
    attention_kernel<<<dim3(S1 / AR, BB * NH), 256, asmem>>>(qbuf, kvbuf, atth);
    // 6) out = att @ wo^T + bo
    gemm_h<<<dim3(QD / 128, (BB * S1) / 128), 256, GSM>>>(atth, woh, bo, out, BB * S1, QD, QD);
}

// round 15
// speedup vs baseline: 4.4009x; 2.1496x over previous
#include <cuda_runtime.h>
#include <cuda_fp16.h>
#include <math.h>

#define BB 8
#define S1 4096
#define S2 256
#define NH 16
#define HD 64
#define QD 1024
#define KVD 2048
#define EPSF 1e-6f
#define SCALEF 0.125f

#define PADK 40                 // halfs per smem row (32 + 8 pad)
#define OPH (128 * PADK)        // 5120 halfs per operand tile
#define STH (2 * OPH)
#define NST 3
#define GSM (NST * STH * 2)     // 61440 bytes

// attention smem layout (bytes)
#define AOFF_K 9216             // Q: 64*72*2
#define AOFF_V 46080            // K: 256*72*2
#define AOFF_S 80640            // Vt: 64*270*2
#define AOFF_P 147200           // S: 64*260*4
#define ASMEM  180992           // P: 64*264*2

// ---------------- scratch (device globals; no allocation allowed) ----------
__device__ float g_q[(size_t)BB * S1 * QD];
__device__ float g_kv[(size_t)BB * S2 * KVD];
__device__ __half g_xh[(size_t)BB * S1 * QD];
__device__ __half g_yh[(size_t)BB * S2 * KVD];
__device__ __half g_wqh[(size_t)QD * QD];
__device__ __half g_wkvh[(size_t)2 * QD * KVD];
__device__ __half g_woh[(size_t)QD * QD];
__device__ __half g_atth[(size_t)BB * S1 * QD];
__device__ __half g_qh[(size_t)BB * S1 * QD];
__device__ __half g_kh[(size_t)BB * S2 * QD];
__device__ __half g_vh[(size_t)BB * S2 * QD];

// ---------------------------------------------------------------------------
__device__ __forceinline__ void mma16816f(float* c, const unsigned* a, const unsigned* b)
{
    asm volatile(
        "mma.sync.aligned.m16n8k16.row.col.f32.f16.f16.f32 "
        "{%0,%1,%2,%3}, {%4,%5,%6,%7}, {%8,%9}, {%0,%1,%2,%3};"
        : "+f"(c[0]), "+f"(c[1]), "+f"(c[2]), "+f"(c[3])
        : "r"(a[0]), "r"(a[1]), "r"(a[2]), "r"(a[3]), "r"(b[0]), "r"(b[1]));
}

__device__ __forceinline__ unsigned pack_h2(__half lo, __half hi)
{
    return (unsigned)__half_as_ushort(lo) | ((unsigned)__half_as_ushort(hi) << 16);
}

__device__ __forceinline__ void cp16cg(__half* dst, const __half* src)
{
    unsigned d = (unsigned)__cvta_generic_to_shared(dst);
    asm volatile("cp.async.cg.shared.global [%0], [%1], 16;" :: "r"(d), "l"(src));
}
__device__ __forceinline__ void cp_commit() { asm volatile("cp.async.commit_group;" ::: "memory"); }
__device__ __forceinline__ void cp_wait1()  { asm volatile("cp.async.wait_group 1;" ::: "memory"); }

// ---------------------------------------------------------------------------
__global__ void to_half(const float* __restrict__ in, __half* __restrict__ out, int n4)
{
    int i = blockIdx.x * blockDim.x + threadIdx.x;
    if (i >= n4) return;
    float4 v = ((const float4*)in)[i];
    ((uint2*)out)[i] = make_uint2(
        pack_h2(__float2half_rn(v.x), __float2half_rn(v.y)),
        pack_h2(__float2half_rn(v.z), __float2half_rn(v.w)));
}

// Extract V half of kv -> fp16.  524288 float4 chunks.
__global__ void v_half(const float* __restrict__ kv, __half* __restrict__ vh)
{
    int i = blockIdx.x * blockDim.x + threadIdx.x;
    if (i >= (BB * S2) * 256) return;
    int row = i >> 8, c = i & 255;
    float4 v = *(const float4*)(kv + (size_t)row * KVD + QD + c * 4);
    *(uint2*)(vh + (size_t)row * QD + c * 4) = make_uint2(
        pack_h2(__float2half_rn(v.x), __float2half_rn(v.y)),
        pack_h2(__float2half_rn(v.z), __float2half_rn(v.w)));
}

// ---------------------------------------------------------------------------
// fp16 GEMM: C = A @ W^T + bias (unchanged from R13)
// ---------------------------------------------------------------------------
__device__ __forceinline__ void issue_stage(
    __half* sh, int s, const __half* Ab, const __half* Wb, int K, int kc, int tid)
{
    __half* base = sh + s * STH;
#pragma unroll
    for (int i = 0; i < 2; i++) {
        int c = tid + i * 256;
        int row = c >> 2;
        int seg = c & 3;
        int soff = row * PADK + seg * 8;
        size_t goff = (size_t)row * K + kc * 32 + seg * 8;
        cp16cg(base + soff, Ab + goff);
        cp16cg(base + OPH + soff, Wb + goff);
    }
}

__global__ __launch_bounds__(256) void gemm_h(
    const __half* __restrict__ A, const __half* __restrict__ W,
    const float* __restrict__ bias, float* __restrict__ C,
    int M, int N, int K)
{
    extern __shared__ __half sh[];
    int tid = threadIdx.x;
    int wid = tid >> 5, lane = tid & 31;
    int wm = wid & 3, wn = wid >> 2;
    int g = lane >> 2, t = lane & 3;

    const __half* Ab = A + (size_t)blockIdx.y * 128 * K;
    const __half* Wb = W + (size_t)blockIdx.x * 128 * K;

    float acc[2][8][4];
#pragma unroll
    for (int mi = 0; mi < 2; mi++)
#pragma unroll
        for (int ni = 0; ni < 8; ni++)
#pragma unroll
            for (int r = 0; r < 4; r++) acc[mi][ni][r] = 0.0f;

    int nch = K >> 5;
    issue_stage(sh, 0, Ab, Wb, K, 0, tid);
    cp_commit();
    issue_stage(sh, 1, Ab, Wb, K, 1, tid);
    cp_commit();

    int cur = 0;
    for (int ki = 0; ki < nch; ki++) {
        cp_wait1();
        __syncthreads();
        int nk = ki + 2;
        if (nk < nch) issue_stage(sh, (cur + 2) % NST, Ab, Wb, K, nk, tid);
        cp_commit();

        const __half* As = sh + cur * STH;
        const __half* Bs = As + OPH;
#pragma unroll
        for (int k0 = 0; k0 < 32; k0 += 16) {
            unsigned ah[2][4];
#pragma unroll
            for (int mi = 0; mi < 2; mi++) {
                int rb = wm * 32 + mi * 16;
                int o00 = (rb + g) * PADK + k0 + 2 * t;
                int o10 = (rb + g + 8) * PADK + k0 + 2 * t;
                ah[mi][0] = *(const unsigned*)&As[o00];
                ah[mi][1] = *(const unsigned*)&As[o10];
                ah[mi][2] = *(const unsigned*)&As[o00 + 8];
                ah[mi][3] = *(const unsigned*)&As[o10 + 8];
            }
#pragma unroll
            for (int ni = 0; ni < 8; ni++) {
                int ob = (wn * 64 + ni * 8 + g) * PADK + k0 + 2 * t;
                unsigned bh[2];
                bh[0] = *(const unsigned*)&Bs[ob];
                bh[1] = *(const unsigned*)&Bs[ob + 8];
#pragma unroll
                for (int mi = 0; mi < 2; mi++) mma16816f(acc[mi][ni], ah[mi], bh);
            }
        }
        cur = (cur + 1) % NST;
    }

#pragma unroll
    for (int mi = 0; mi < 2; mi++) {
#pragma unroll
        for (int ni = 0; ni < 8; ni++) {
            int col = blockIdx.x * 128 + wn * 64 + ni * 8 + 2 * t;
            float b0 = bias[col], b1 = bias[col + 1];
            size_t row0 = (size_t)blockIdx.y * 128 + wm * 32 + mi * 16 + g;
            *(float2*)(C + row0 * N + col) =
                make_float2(acc[mi][ni][0] + b0, acc[mi][ni][1] + b1);
            *(float2*)(C + (row0 + 8) * N + col) =
                make_float2(acc[mi][ni][2] + b0, acc[mi][ni][3] + b1);
        }
    }
}

// ---------------------------------------------------------------------------
// LayerNorm + 2D RoPE on Q -> fp16 out. One warp per (b, s, h).
// ---------------------------------------------------------------------------
__global__ void ln_rope_q(const float* __restrict__ q, __half* __restrict__ qo,
                          const float* __restrict__ g, const float* __restrict__ bt)
{
    int gw = (blockIdx.x * blockDim.x + threadIdx.x) >> 5;
    int lane = threadIdx.x & 31;
    if (gw >= BB * S1 * NH) return;
    const float2* p = (const float2*)(q + (size_t)gw * HD);
    float2 v = p[lane];
    float sum = v.x + v.y;
    float sq = v.x * v.x + v.y * v.y;
#pragma unroll
    for (int o = 16; o; o >>= 1) {
        sum += __shfl_xor_sync(0xffffffffu, sum, o);
        sq  += __shfl_xor_sync(0xffffffffu, sq, o);
    }
    float mu = sum * (1.0f / HD);
    float var = sq * (1.0f / HD) - mu * mu;
    float rstd = rsqrtf(var + EPSF);
    float e  = (v.x - mu) * rstd * g[2 * lane]     + bt[2 * lane];
    float od = (v.y - mu) * rstd * g[2 * lane + 1] + bt[2 * lane + 1];

    int s = (gw / NH) & (S1 - 1);
    int hh = s >> 6, ww = s & 63;
    int t = lane >> 1;
    float inv = exp10f(-0.25f * (float)t);
    float ang = ((lane & 1) ? (float)ww : (float)hh) * inv;
    float n = rintf(ang * 0.15915494309189535f);
    ang -= n * 6.283185307179586f;
    float sn, cs;
    sincosf(ang, &sn, &cs);
    float re = e * cs - od * sn;
    float ro = e * sn + od * cs;
    *(unsigned*)(qo + (size_t)gw * HD + 2 * lane) =
        pack_h2(__float2half_rn(re), __float2half_rn(ro));
}

// LayerNorm on K -> fp16 out. One warp per (b, s2, h).
__global__ void ln_k(const float* __restrict__ kv, __half* __restrict__ ko,
                     const float* __restrict__ g, const float* __restrict__ bt)
{
    int gw = (blockIdx.x * blockDim.x + threadIdx.x) >> 5;
    int lane = threadIdx.x & 31;
    if (gw >= BB * S2 * NH) return;
    int row = gw / NH, h = gw % NH;
    const float2* p = (const float2*)(kv + (size_t)row * KVD + h * HD);
    float2 v = p[lane];
    float sum = v.x + v.y;
    float sq = v.x * v.x + v.y * v.y;
#pragma unroll
    for (int o = 16; o; o >>= 1) {
        sum += __shfl_xor_sync(0xffffffffu, sum, o);
        sq  += __shfl_xor_sync(0xffffffffu, sq, o);
    }
    float mu = sum * (1.0f / HD);
    float var = sq * (1.0f / HD) - mu * mu;
    float rstd = rsqrtf(var + EPSF);
    float e  = (v.x - mu) * rstd * g[2 * lane]     + bt[2 * lane];
    float od = (v.y - mu) * rstd * g[2 * lane + 1] + bt[2 * lane + 1];
    *(unsigned*)(ko + (size_t)gw * HD + 2 * lane) =
        pack_h2(__float2half_rn(e), __float2half_rn(od));
}

// ---------------------------------------------------------------------------
// Tensor-core attention. Block = 64 q-rows of one (b,h). S2=256 keys.
// QK^T (fp16 MMA) -> fp32 softmax -> PV (fp16 MMA) -> fp16 out (for GEMM3).
// ---------------------------------------------------------------------------
__global__ __launch_bounds__(256) void attn_mma(
    const __half* __restrict__ qh, const __half* __restrict__ kh,
    const __half* __restrict__ vh, __half* __restrict__ oh)
{
    extern __shared__ char smb[];
    __half* Qs = (__half*)smb;                    // 64 x 72
    __half* Ks = (__half*)(smb + AOFF_K);         // 256 x 72
    __half* Vt = (__half*)(smb + AOFF_V);         // 64(d) x 270(k)
    float*  Ss = (float*)(smb + AOFF_S);          // 64 x 260
    __half* Ps = (__half*)(smb + AOFF_P);         // 64 x 264

    int bh = blockIdx.y;
    int b = bh >> 4, h = bh & 15;
    int r0 = blockIdx.x * 64;
    int tid = threadIdx.x;
    int wid = tid >> 5, lane = tid & 31;
    int g = lane >> 2, t = lane & 3;

    // loads: Q 64x64, K 256x64 (16B chunks), V transposed
    for (int c = tid; c < 512; c += 256) {
        int r = c >> 3, seg = c & 7;
        const __half* src = qh + (((size_t)b * S1 + r0 + r) * NH + h) * HD + seg * 8;
        *(uint4*)&Qs[r * 72 + seg * 8] = *(const uint4*)src;
    }
    for (int c = tid; c < 2048; c += 256) {
        int r = c >> 3, seg = c & 7;
        const __half* src = kh + (((size_t)b * S2 + r) * NH + h) * HD + seg * 8;
        *(uint4*)&Ks[r * 72 + seg * 8] = *(const uint4*)src;
    }
    for (int idx = tid; idx < 8192; idx += 256) {
        int k = idx >> 5, dp = idx & 31;
        unsigned v2 = *(const unsigned*)(vh + (((size_t)b * S2 + k) * NH + h) * HD + dp * 2);
        Vt[(dp * 2) * 270 + k]     = __ushort_as_half((unsigned short)(v2 & 0xffffu));
        Vt[(dp * 2 + 1) * 270 + k] = __ushort_as_half((unsigned short)(v2 >> 16));
    }
    __syncthreads();

    // ---- QK^T: M=64 (2 warps), N=256 (4 warps), K=64 ----
    {
        int wm = wid & 1, wn = wid >> 1;
        float acc[2][8][4];
#pragma unroll
        for (int mi = 0; mi < 2; mi++)
#pragma unroll
            for (int ni = 0; ni < 8; ni++)
#pragma unroll
                for (int r = 0; r < 4; r++) acc[mi][ni][r] = 0.0f;

#pragma unroll
        for (int k0 = 0; k0 < 64; k0 += 16) {
            unsigned aq[2][4];
#pragma unroll
            for (int mi = 0; mi < 2; mi++) {
                int rb = wm * 32 + mi * 16;
                int o00 = (rb + g) * 72 + k0 + 2 * t;
                int o10 = (rb + g + 8) * 72 + k0 + 2 * t;
                aq[mi][0] = *(const unsigned*)&Qs[o00];
                aq[mi][1] = *(const unsigned*)&Qs[o10];
                aq[mi][2] = *(const unsigned*)&Qs[o00 + 8];
                aq[mi][3] = *(const unsigned*)&Qs[o10 + 8];
            }
#pragma unroll
            for (int ni = 0; ni < 8; ni++) {
                int ob = (wn * 64 + ni * 8 + g) * 72 + k0 + 2 * t;
                unsigned bk[2];
                bk[0] = *(const unsigned*)&Ks[ob];
                bk[1] = *(const unsigned*)&Ks[ob + 8];
#pragma unroll
                for (int mi = 0; mi < 2; mi++) mma16816f(acc[mi][ni], aq[mi], bk);
            }
        }
        // scores -> Ss (scaled)
#pragma unroll
        for (int mi = 0; mi < 2; mi++) {
#pragma unroll
            for (int ni = 0; ni < 8; ni++) {
                int row = wm * 32 + mi * 16 + g;
                int col = wn * 64 + ni * 8 + 2 * t;
                *(float2*)&Ss[row * 260 + col] =
                    make_float2(acc[mi][ni][0] * SCALEF, acc[mi][ni][1] * SCALEF);
                *(float2*)&Ss[(row + 8) * 260 + col] =
                    make_float2(acc[mi][ni][2] * SCALEF, acc[mi][ni][3] * SCALEF);
            }
        }
    }
    __syncthreads();

    // ---- softmax (fp32), write P as fp16 ----
    for (int r = wid; r < 64; r += 8) {
        float* srow = Ss + r * 260;
        float vals[8];
        float m = -1e30f;
#pragma unroll
        for (int i = 0; i < 8; i++) { vals[i] = srow[lane + 32 * i]; m = fmaxf(m, vals[i]); }
#pragma unroll
        for (int o = 16; o; o >>= 1) m = fmaxf(m, __shfl_xor_sync(0xffffffffu, m, o));
        float l = 0.0f;
#pragma unroll
        for (int i = 0; i < 8; i++) { vals[i] = __expf(vals[i] - m); l += vals[i]; }
#pragma unroll
        for (int o = 16; o; o >>= 1) l += __shfl_xor_sync(0xffffffffu, l, o);
        float rl = 1.0f / l;
#pragma unroll
        for (int i = 0; i < 8; i++)
            Ps[r * 264 + lane + 32 * i] = __float2half_rn(vals[i] * rl);
    }
    __syncthreads();

    // ---- PV: M=64 (2 warps), N=64 (4 warps x 16), K=256 ----
    {
        int wm = wid & 1, wn = wid >> 1;
        float acc[2][2][4];
#pragma unroll
        for (int mi = 0; mi < 2; mi++)
#pragma unroll
            for (int ni = 0; ni < 2; ni++)
#pragma unroll
                for (int r = 0; r < 4; r++) acc[mi][ni][r] = 0.0f;

#pragma unroll 4
        for (int k0 = 0; k0 < 256; k0 += 16) {
            unsigned ap[2][4];
#pragma unroll
            for (int mi = 0; mi < 2; mi++) {
                int rb = wm * 32 + mi * 16;
                int o00 = (rb + g) * 264 + k0 + 2 * t;
                int o10 = (rb + g + 8) * 264 + k0 + 2 * t;
                ap[mi][0] = *(const unsigned*)&Ps[o00];
                ap[mi][1] = *(const unsigned*)&Ps[o10];
                ap[mi][2] = *(const unsigned*)&Ps[o00 + 8];
                ap[mi][3] = *(const unsigned*)&Ps[o10 + 8];
            }
#pragma unroll
            for (int ni = 0; ni < 2; ni++) {
                int ob = (wn * 16 + ni * 8 + g) * 270 + k0 + 2 * t;
                unsigned bv[2];
                bv[0] = *(const unsigned*)&Vt[ob];
                bv[1] = *(const unsigned*)&Vt[ob + 8];
#pragma unroll
                for (int mi = 0; mi < 2; mi++) mma16816f(acc[mi][ni], ap[mi], bv);
            }
        }

        // output -> fp16 (b,s,h,d)
#pragma unroll
        for (int mi = 0; mi < 2; mi++) {
#pragma unroll
            for (int ni = 0; ni < 2; ni++) {
                int row = wm * 32 + mi * 16 + g;
                int col = wn * 16 + ni * 8 + 2 * t;
                size_t o0 = (((size_t)b * S1 + r0 + row) * NH + h) * HD + col;
                size_t o1 = (((size_t)b * S1 + r0 + row + 8) * NH + h) * HD + col;
                *(unsigned*)(oh + o0) =
                    pack_h2(__float2half_rn(acc[mi][ni][0]), __float2half_rn(acc[mi][ni][1]));
                *(unsigned*)(oh + o1) =
                    pack_h2(__float2half_rn(acc[mi][ni][2]), __float2half_rn(acc[mi][ni][3]));
            }
        }
    }
}

// ---------------------------------------------------------------------------
extern "C" void kernel_launch(void* const* d_in, const int* in_sizes, int n_in,
                              void* d_out, int out_size)
{
    (void)in_sizes; (void)n_in; (void)out_size;
    const float* x   = (const float*)d_in[0];
    const float* y   = (const float*)d_in[1];
    const float* wq  = (const float*)d_in[2];
    const float* bq  = (const float*)d_in[3];
    const float* wkv = (const float*)d_in[4];
    const float* bkv = (const float*)d_in[5];
    const float* wo  = (const float*)d_in[6];
    const float* bo  = (const float*)d_in[7];
    const float* qng = (const float*)d_in[8];
    const float* qnb = (const float*)d_in[9];
    const float* kng = (const float*)d_in[10];
    const float* knb = (const float*)d_in[11];
    float* out = (float*)d_out;

    float* qbuf;
    float* kvbuf;
    __half* xh;
    __half* yh;
    __half* wqh;
    __half* wkvh;
    __half* woh;
    __half* atth;
    __half* qh;
    __half* kh;
    __half* vh;
    cudaGetSymbolAddress((void**)&qbuf, g_q);
    cudaGetSymbolAddress((void**)&kvbuf, g_kv);
    cudaGetSymbolAddress((void**)&xh, g_xh);
    cudaGetSymbolAddress((void**)&yh, g_yh);
    cudaGetSymbolAddress((void**)&wqh, g_wqh);
    cudaGetSymbolAddress((void**)&wkvh, g_wkvh);
    cudaGetSymbolAddress((void**)&woh, g_woh);
    cudaGetSymbolAddress((void**)&atth, g_atth);
    cudaGetSymbolAddress((void**)&qh, g_qh);
    cudaGetSymbolAddress((void**)&kh, g_kh);
    cudaGetSymbolAddress((void**)&vh, g_vh);

    // 0) convert inputs to fp16
    int n;
    n = BB * S1 * QD / 4;
    to_half<<<(n + 255) / 256, 256>>>(x, xh, n);
    n = BB * S2 * KVD / 4;
    to_half<<<(n + 255) / 256, 256>>>(y, yh, n);
    n = QD * QD / 4;
    to_half<<<(n + 255) / 256, 256>>>(wq, wqh, n);
    n = 2 * QD * KVD / 4;
    to_half<<<(n + 255) / 256, 256>>>(wkv, wkvh, n);
    n = QD * QD / 4;
    to_half<<<(n + 255) / 256, 256>>>(wo, woh, n);

    cudaFuncSetAttribute(gemm_h, cudaFuncAttributeMaxDynamicSharedMemorySize, GSM);

    // 1) Q = x @ wq^T + bq
    gemm_h<<<dim3(QD / 128, (BB * S1) / 128), 256, GSM>>>(xh, wqh, bq, qbuf, BB * S1, QD, QD);
    // 2) KV = y @ wkv^T + bkv
    gemm_h<<<dim3(KVD / 128, (BB * S2) / 128), 256, GSM>>>(yh, wkvh, bkv, kvbuf, BB * S2, KVD, KVD);
    // 3) LN + RoPE on Q -> fp16
    ln_rope_q<<<(BB * S1 * NH) / 4, 128>>>(qbuf, qh, qng, qnb);
    // 4) LN on K -> fp16; extract V -> fp16
    ln_k<<<(BB * S2 * NH) / 4, 128>>>(kvbuf, kh, kng, knb);
    n = (BB * S2) * 256;
    v_half<<<(n + 255) / 256, 256>>>(kvbuf, vh);
    // 5) tensor-core attention -> fp16
    cudaFuncSetAttribute(attn_mma, cudaFuncAttributeMaxDynamicSharedMemorySize, ASMEM);
    attn_mma<<<dim3(S1 / 64, BB * NH), 256, ASMEM>>>(qh, kh, vh, atth);
    // 6) out = att @ wo^T + bo
    gemm_h<<<dim3(QD / 128, (BB * S1) / 128), 256, GSM>>>(atth, woh, bo, out, BB * S1, QD, QD);
}

// round 17
// speedup vs baseline: 4.6306x; 1.0522x over previous
#include <cuda_runtime.h>
#include <cuda_fp16.h>
#include <math.h>

#define BB 8
#define S1 4096
#define S2 256
#define NH 16
#define HD 64
#define QD 1024
#define KVD 2048
#define EPSF 1e-6f
#define SCALEF 0.125f

#define PADK 40                 // halfs per smem row (32 + 8 pad)
#define OPH (128 * PADK)        // 5120 halfs per operand tile
#define STH (2 * OPH)
#define NST 3
#define GSM (NST * STH * 2)     // 61440 bytes

// attention smem layout (bytes)
#define AOFF_K 9216             // Q: 64*72*2
#define AOFF_V 46080            // K: 256*72*2
#define AOFF_S 80640            // Vt: 64*270*2
#define AOFF_P 147200           // S: 64*260*4
#define ASMEM  180992           // P: 64*264*2

// ---------------- scratch (device globals; no allocation allowed) ----------
__device__ __half g_xh[(size_t)BB * S1 * QD];
__device__ __half g_yh[(size_t)BB * S2 * KVD];
__device__ __half g_wqh[(size_t)QD * QD];
__device__ __half g_wkvh[(size_t)2 * QD * KVD];
__device__ __half g_woh[(size_t)QD * QD];
__device__ __half g_atth[(size_t)BB * S1 * QD];
__device__ __half g_qh[(size_t)BB * S1 * QD];
__device__ __half g_kh[(size_t)BB * S2 * QD];
__device__ __half g_vh[(size_t)BB * S2 * QD];

// ---------------------------------------------------------------------------
__device__ __forceinline__ void mma16816f(float* c, const unsigned* a, const unsigned* b)
{
    asm volatile(
        "mma.sync.aligned.m16n8k16.row.col.f32.f16.f16.f32 "
        "{%0,%1,%2,%3}, {%4,%5,%6,%7}, {%8,%9}, {%0,%1,%2,%3};"
        : "+f"(c[0]), "+f"(c[1]), "+f"(c[2]), "+f"(c[3])
        : "r"(a[0]), "r"(a[1]), "r"(a[2]), "r"(a[3]), "r"(b[0]), "r"(b[1]));
}

__device__ __forceinline__ unsigned pack_h2(__half lo, __half hi)
{
    return (unsigned)__half_as_ushort(lo) | ((unsigned)__half_as_ushort(hi) << 16);
}

__device__ __forceinline__ void cp16cg(__half* dst, const __half* src)
{
    unsigned d = (unsigned)__cvta_generic_to_shared(dst);
    asm volatile("cp.async.cg.shared.global [%0], [%1], 16;" :: "r"(d), "l"(src));
}
__device__ __forceinline__ void cp_commit() { asm volatile("cp.async.commit_group;" ::: "memory"); }
__device__ __forceinline__ void cp_wait1()  { asm volatile("cp.async.wait_group 1;" ::: "memory"); }

// ---------------------------------------------------------------------------
__global__ void to_half(const float* __restrict__ in, __half* __restrict__ out, int n4)
{
    int i = blockIdx.x * blockDim.x + threadIdx.x;
    if (i >= n4) return;
    float4 v = ((const float4*)in)[i];
    ((uint2*)out)[i] = make_uint2(
        pack_h2(__float2half_rn(v.x), __float2half_rn(v.y)),
        pack_h2(__float2half_rn(v.z), __float2half_rn(v.w)));
}

// ---------------------------------------------------------------------------
// Shared GEMM mainloop machinery (128x128 tile, BK=32, 3-stage cp.async)
// ---------------------------------------------------------------------------
__device__ __forceinline__ void issue_stage(
    __half* sh, int s, const __half* Ab, const __half* Wb, int K, int kc, int tid)
{
    __half* base = sh + s * STH;
#pragma unroll
    for (int i = 0; i < 2; i++) {
        int c = tid + i * 256;
        int row = c >> 2;
        int seg = c & 3;
        int soff = row * PADK + seg * 8;
        size_t goff = (size_t)row * K + kc * 32 + seg * 8;
        cp16cg(base + soff, Ab + goff);
        cp16cg(base + OPH + soff, Wb + goff);
    }
}

// mainloop: fills acc[2][8][4]. Must be called by all 256 threads.
__device__ __forceinline__ void gemm_mainloop(
    __half* sh, const __half* Ab, const __half* Wb, int K,
    int tid, int wm, int wn, int g, int t, float acc[2][8][4])
{
#pragma unroll
    for (int mi = 0; mi < 2; mi++)
#pragma unroll
        for (int ni = 0; ni < 8; ni++)
#pragma unroll
            for (int r = 0; r < 4; r++) acc[mi][ni][r] = 0.0f;

    int nch = K >> 5;
    issue_stage(sh, 0, Ab, Wb, K, 0, tid);
    cp_commit();
    issue_stage(sh, 1, Ab, Wb, K, 1, tid);
    cp_commit();

    int cur = 0;
    for (int ki = 0; ki < nch; ki++) {
        cp_wait1();
        __syncthreads();
        int nk = ki + 2;
        if (nk < nch) issue_stage(sh, (cur + 2) % NST, Ab, Wb, K, nk, tid);
        cp_commit();

        const __half* As = sh + cur * STH;
        const __half* Bs = As + OPH;
#pragma unroll
        for (int k0 = 0; k0 < 32; k0 += 16) {
            unsigned ah[2][4];
#pragma unroll
            for (int mi = 0; mi < 2; mi++) {
                int rb = wm * 32 + mi * 16;
                int o00 = (rb + g) * PADK + k0 + 2 * t;
                int o10 = (rb + g + 8) * PADK + k0 + 2 * t;
                ah[mi][0] = *(const unsigned*)&As[o00];
                ah[mi][1] = *(const unsigned*)&As[o10];
                ah[mi][2] = *(const unsigned*)&As[o00 + 8];
                ah[mi][3] = *(const unsigned*)&As[o10 + 8];
            }
#pragma unroll
            for (int ni = 0; ni < 8; ni++) {
                int ob = (wn * 64 + ni * 8 + g) * PADK + k0 + 2 * t;
                unsigned bh[2];
                bh[0] = *(const unsigned*)&Bs[ob];
                bh[1] = *(const unsigned*)&Bs[ob + 8];
#pragma unroll
                for (int mi = 0; mi < 2; mi++) mma16816f(acc[mi][ni], ah[mi], bh);
            }
        }
        cur = (cur + 1) % NST;
    }
}

// ---------------------------------------------------------------------------
// GEMM3: C(fp32) = A @ W^T + bias
// ---------------------------------------------------------------------------
__global__ __launch_bounds__(256) void gemm_h(
    const __half* __restrict__ A, const __half* __restrict__ W,
    const float* __restrict__ bias, float* __restrict__ C,
    int M, int N, int K)
{
    extern __shared__ __half sh[];
    int tid = threadIdx.x;
    int wid = tid >> 5, lane = tid & 31;
    int wm = wid & 3, wn = wid >> 2;
    int g = lane >> 2, t = lane & 3;

    const __half* Ab = A + (size_t)blockIdx.y * 128 * K;
    const __half* Wb = W + (size_t)blockIdx.x * 128 * K;

    float acc[2][8][4];
    gemm_mainloop(sh, Ab, Wb, K, tid, wm, wn, g, t, acc);

#pragma unroll
    for (int mi = 0; mi < 2; mi++) {
#pragma unroll
        for (int ni = 0; ni < 8; ni++) {
            int col = blockIdx.x * 128 + wn * 64 + ni * 8 + 2 * t;
            float b0 = bias[col], b1 = bias[col + 1];
            size_t row0 = (size_t)blockIdx.y * 128 + wm * 32 + mi * 16 + g;
            *(float2*)(C + row0 * N + col) =
                make_float2(acc[mi][ni][0] + b0, acc[mi][ni][1] + b1);
            *(float2*)(C + (row0 + 8) * N + col) =
                make_float2(acc[mi][ni][2] + b0, acc[mi][ni][3] + b1);
        }
    }
}

// ---------------------------------------------------------------------------
// GEMM1 fused: Q = LN_head(x @ wq^T + bq) + RoPE  -> fp16 qh
// One warp-tile col-chunk (wn) == exactly one head (64 cols).
// ---------------------------------------------------------------------------
__global__ __launch_bounds__(256) void gemm_q(
    const __half* __restrict__ A, const __half* __restrict__ W,
    const float* __restrict__ bias, __half* __restrict__ Qout,
    const float* __restrict__ gam, const float* __restrict__ bet,
    int M, int N, int K)
{
    extern __shared__ __half sh[];
    int tid = threadIdx.x;
    int wid = tid >> 5, lane = tid & 31;
    int wm = wid & 3, wn = wid >> 2;
    int g = lane >> 2, t = lane & 3;

    const __half* Ab = A + (size_t)blockIdx.y * 128 * K;
    const __half* Wb = W + (size_t)blockIdx.x * 128 * K;

    float acc[2][8][4];
    gemm_mainloop(sh, Ab, Wb, K, tid, wm, wn, g, t, acc);

    int colbase = blockIdx.x * 128 + wn * 64;   // head-aligned
#pragma unroll
    for (int mi = 0; mi < 2; mi++) {
        size_t grow0 = (size_t)blockIdx.y * 128 + wm * 32 + mi * 16 + g;
#pragma unroll
        for (int hf = 0; hf < 2; hf++) {
            size_t grow = grow0 + hf * 8;
            int ab = hf * 2;
            float v0[8], v1[8];
            float sum = 0.0f, sq = 0.0f;
#pragma unroll
            for (int ni = 0; ni < 8; ni++) {
                int hc = ni * 8 + 2 * t;
                v0[ni] = acc[mi][ni][ab]     + bias[colbase + hc];
                v1[ni] = acc[mi][ni][ab + 1] + bias[colbase + hc + 1];
                sum += v0[ni] + v1[ni];
                sq  += v0[ni] * v0[ni] + v1[ni] * v1[ni];
            }
            sum += __shfl_xor_sync(0xffffffffu, sum, 1);
            sq  += __shfl_xor_sync(0xffffffffu, sq, 1);
            sum += __shfl_xor_sync(0xffffffffu, sum, 2);
            sq  += __shfl_xor_sync(0xffffffffu, sq, 2);
            float mu = sum * (1.0f / HD);
            float var = sq * (1.0f / HD) - mu * mu;
            float rstd = rsqrtf(var + EPSF);
            int s = (int)(grow & (S1 - 1));
            int hh = s >> 6, ww = s & 63;
#pragma unroll
            for (int ni = 0; ni < 8; ni++) {
                int hc = ni * 8 + 2 * t;
                float e  = (v0[ni] - mu) * rstd * gam[hc]     + bet[hc];
                float od = (v1[ni] - mu) * rstd * gam[hc + 1] + bet[hc + 1];
                int j = ni * 4 + t;            // pair index within head
                int tix = j >> 1;
                float inv = exp10f(-0.25f * (float)tix);
                float ang = ((j & 1) ? (float)ww : (float)hh) * inv;
                float nr = rintf(ang * 0.15915494309189535f);
                ang -= nr * 6.283185307179586f;
                float sn, cs;
                sincosf(ang, &sn, &cs);
                *(unsigned*)(Qout + grow * N + colbase + hc) =
                    pack_h2(__float2half_rn(e * cs - od * sn),
                            __float2half_rn(e * sn + od * cs));
            }
        }
    }
}

// ---------------------------------------------------------------------------
// GEMM2 fused: KV = y @ wkv^T + bkv; cols<1024 -> LN_head -> kh; else -> vh.
// ---------------------------------------------------------------------------
__global__ __launch_bounds__(256) void gemm_kv(
    const __half* __restrict__ A, const __half* __restrict__ W,
    const float* __restrict__ bias,
    __half* __restrict__ Kout, __half* __restrict__ Vout,
    const float* __restrict__ gam, const float* __restrict__ bet,
    int M, int N, int K)
{
    extern __shared__ __half sh[];
    int tid = threadIdx.x;
    int wid = tid >> 5, lane = tid & 31;
    int wm = wid & 3, wn = wid >> 2;
    int g = lane >> 2, t = lane & 3;

    const __half* Ab = A + (size_t)blockIdx.y * 128 * K;
    const __half* Wb = W + (size_t)blockIdx.x * 128 * K;

    float acc[2][8][4];
    gemm_mainloop(sh, Ab, Wb, K, tid, wm, wn, g, t, acc);

    int colbase = blockIdx.x * 128 + wn * 64;
    bool isK = colbase < QD;
#pragma unroll
    for (int mi = 0; mi < 2; mi++) {
        size_t grow0 = (size_t)blockIdx.y * 128 + wm * 32 + mi * 16 + g;
#pragma unroll
        for (int hf = 0; hf < 2; hf++) {
            size_t grow = grow0 + hf * 8;
            int ab = hf * 2;
            float v0[8], v1[8];
            float sum = 0.0f, sq = 0.0f;
#pragma unroll
            for (int ni = 0; ni < 8; ni++) {
                int hc = ni * 8 + 2 * t;
                v0[ni] = acc[mi][ni][ab]     + bias[colbase + hc];
                v1[ni] = acc[mi][ni][ab + 1] + bias[colbase + hc + 1];
                sum += v0[ni] + v1[ni];
                sq  += v0[ni] * v0[ni] + v1[ni] * v1[ni];
            }
            if (isK) {
                sum += __shfl_xor_sync(0xffffffffu, sum, 1);
                sq  += __shfl_xor_sync(0xffffffffu, sq, 1);
                sum += __shfl_xor_sync(0xffffffffu, sum, 2);
                sq  += __shfl_xor_sync(0xffffffffu, sq, 2);
                float mu = sum * (1.0f / HD);
                float var = sq * (1.0f / HD) - mu * mu;
                float rstd = rsqrtf(var + EPSF);
#pragma unroll
                for (int ni = 0; ni < 8; ni++) {
                    int hc = ni * 8 + 2 * t;
                    float e  = (v0[ni] - mu) * rstd * gam[hc]     + bet[hc];
                    float od = (v1[ni] - mu) * rstd * gam[hc + 1] + bet[hc + 1];
                    *(unsigned*)(Kout + grow * QD + colbase + hc) =
                        pack_h2(__float2half_rn(e), __float2half_rn(od));
                }
            } else {
#pragma unroll
                for (int ni = 0; ni < 8; ni++) {
                    int hc = ni * 8 + 2 * t;
                    *(unsigned*)(Vout + grow * QD + (colbase - QD) + hc) =
                        pack_h2(__float2half_rn(v0[ni]), __float2half_rn(v1[ni]));
                }
            }
        }
    }
}

// ---------------------------------------------------------------------------
// Tensor-core attention (unchanged from R15).
// ---------------------------------------------------------------------------
__global__ __launch_bounds__(256) void attn_mma(
    const __half* __restrict__ qh, const __half* __restrict__ kh,
    const __half* __restrict__ vh, __half* __restrict__ oh)
{
    extern __shared__ char smb[];
    __half* Qs = (__half*)smb;
    __half* Ks = (__half*)(smb + AOFF_K);
    __half* Vt = (__half*)(smb + AOFF_V);
    float*  Ss = (float*)(smb + AOFF_S);
    __half* Ps = (__half*)(smb + AOFF_P);

    int bh = blockIdx.y;
    int b = bh >> 4, h = bh & 15;
    int r0 = blockIdx.x * 64;
    int tid = threadIdx.x;
    int wid = tid >> 5, lane = tid & 31;
    int g = lane >> 2, t = lane & 3;

    for (int c = tid; c < 512; c += 256) {
        int r = c >> 3, seg = c & 7;
        const __half* src = qh + (((size_t)b * S1 + r0 + r) * NH + h) * HD + seg * 8;
        *(uint4*)&Qs[r * 72 + seg * 8] = *(const uint4*)src;
    }
    for (int c = tid; c < 2048; c += 256) {
        int r = c >> 3, seg = c & 7;
        const __half* src = kh + (((size_t)b * S2 + r) * NH + h) * HD + seg * 8;
        *(uint4*)&Ks[r * 72 + seg * 8] = *(const uint4*)src;
    }
    for (int idx = tid; idx < 8192; idx += 256) {
        int k = idx >> 5, dp = idx & 31;
        unsigned v2 = *(const unsigned*)(vh + (((size_t)b * S2 + k) * NH + h) * HD + dp * 2);
        Vt[(dp * 2) * 270 + k]     = __ushort_as_half((unsigned short)(v2 & 0xffffu));
        Vt[(dp * 2 + 1) * 270 + k] = __ushort_as_half((unsigned short)(v2 >> 16));
    }
    __syncthreads();

    {
        int wm = wid & 1, wn = wid >> 1;
        float acc[2][8][4];
#pragma unroll
        for (int mi = 0; mi < 2; mi++)
#pragma unroll
            for (int ni = 0; ni < 8; ni++)
#pragma unroll
                for (int r = 0; r < 4; r++) acc[mi][ni][r] = 0.0f;

#pragma unroll
        for (int k0 = 0; k0 < 64; k0 += 16) {
            unsigned aq[2][4];
#pragma unroll
            for (int mi = 0; mi < 2; mi++) {
                int rb = wm * 32 + mi * 16;
                int o00 = (rb + g) * 72 + k0 + 2 * t;
                int o10 = (rb + g + 8) * 72 + k0 + 2 * t;
                aq[mi][0] = *(const unsigned*)&Qs[o00];
                aq[mi][1] = *(const unsigned*)&Qs[o10];
                aq[mi][2] = *(const unsigned*)&Qs[o00 + 8];
                aq[mi][3] = *(const unsigned*)&Qs[o10 + 8];
            }
#pragma unroll
            for (int ni = 0; ni < 8; ni++) {
                int ob = (wn * 64 + ni * 8 + g) * 72 + k0 + 2 * t;
                unsigned bk[2];
                bk[0] = *(const unsigned*)&Ks[ob];
                bk[1] = *(const unsigned*)&Ks[ob + 8];
#pragma unroll
                for (int mi = 0; mi < 2; mi++) mma16816f(acc[mi][ni], aq[mi], bk);
            }
        }
#pragma unroll
        for (int mi = 0; mi < 2; mi++) {
#pragma unroll
            for (int ni = 0; ni < 8; ni++) {
                int row = wm * 32 + mi * 16 + g;
                int col = wn * 64 + ni * 8 + 2 * t;
                *(float2*)&Ss[row * 260 + col] =
                    make_float2(acc[mi][ni][0] * SCALEF, acc[mi][ni][1] * SCALEF);
                *(float2*)&Ss[(row + 8) * 260 + col] =
                    make_float2(acc[mi][ni][2] * SCALEF, acc[mi][ni][3] * SCALEF);
            }
        }
    }
    __syncthreads();

    for (int r = wid; r < 64; r += 8) {
        float* srow = Ss + r * 260;
        float vals[8];
        float m = -1e30f;
#pragma unroll
        for (int i = 0; i < 8; i++) { vals[i] = srow[lane + 32 * i]; m = fmaxf(m, vals[i]); }
#pragma unroll
        for (int o = 16; o; o >>= 1) m = fmaxf(m, __shfl_xor_sync(0xffffffffu, m, o));
        float l = 0.0f;
#pragma unroll
        for (int i = 0; i < 8; i++) { vals[i] = __expf(vals[i] - m); l += vals[i]; }
#pragma unroll
        for (int o = 16; o; o >>= 1) l += __shfl_xor_sync(0xffffffffu, l, o);
        float rl = 1.0f / l;
#pragma unroll
        for (int i = 0; i < 8; i++)
            Ps[r * 264 + lane + 32 * i] = __float2half_rn(vals[i] * rl);
    }
    __syncthreads();

    {
        int wm = wid & 1, wn = wid >> 1;
        float acc[2][2][4];
#pragma unroll
        for (int mi = 0; mi < 2; mi++)
#pragma unroll
            for (int ni = 0; ni < 2; ni++)
#pragma unroll
                for (int r = 0; r < 4; r++) acc[mi][ni][r] = 0.0f;

#pragma unroll 4
        for (int k0 = 0; k0 < 256; k0 += 16) {
            unsigned ap[2][4];
#pragma unroll
            for (int mi = 0; mi < 2; mi++) {
                int rb = wm * 32 + mi * 16;
                int o00 = (rb + g) * 264 + k0 + 2 * t;
                int o10 = (rb + g + 8) * 264 + k0 + 2 * t;
                ap[mi][0] = *(const unsigned*)&Ps[o00];
                ap[mi][1] = *(const unsigned*)&Ps[o10];
                ap[mi][2] = *(const unsigned*)&Ps[o00 + 8];
                ap[mi][3] = *(const unsigned*)&Ps[o10 + 8];
            }
#pragma unroll
            for (int ni = 0; ni < 2; ni++) {
                int ob = (wn * 16 + ni * 8 + g) * 270 + k0 + 2 * t;
                unsigned bv[2];
                bv[0] = *(const unsigned*)&Vt[ob];
                bv[1] = *(const unsigned*)&Vt[ob + 8];
#pragma unroll
                for (int mi = 0; mi < 2; mi++) mma16816f(acc[mi][ni], ap[mi], bv);
            }
        }

#pragma unroll
        for (int mi = 0; mi < 2; mi++) {
#pragma unroll
            for (int ni = 0; ni < 2; ni++) {
                int row = wm * 32 + mi * 16 + g;
                int col = wn * 16 + ni * 8 + 2 * t;
                size_t o0 = (((size_t)b * S1 + r0 + row) * NH + h) * HD + col;
                size_t o1 = (((size_t)b * S1 + r0 + row + 8) * NH + h) * HD + col;
                *(unsigned*)(oh + o0) =
                    pack_h2(__float2half_rn(acc[mi][ni][0]), __float2half_rn(acc[mi][ni][1]));
                *(unsigned*)(oh + o1) =
                    pack_h2(__float2half_rn(acc[mi][ni][2]), __float2half_rn(acc[mi][ni][3]));
            }
        }
    }
}

// ---------------------------------------------------------------------------
extern "C" void kernel_launch(void* const* d_in, const int* in_sizes, int n_in,
                              void* d_out, int out_size)
{
    (void)in_sizes; (void)n_in; (void)out_size;
    const float* x   = (const float*)d_in[0];
    const float* y   = (const float*)d_in[1];
    const float* wq  = (const float*)d_in[2];
    const float* bq  = (const float*)d_in[3];
    const float* wkv = (const float*)d_in[4];
    const float* bkv = (const float*)d_in[5];
    const float* wo  = (const float*)d_in[6];
    const float* bo  = (const float*)d_in[7];
    const float* qng = (const float*)d_in[8];
    const float* qnb = (const float*)d_in[9];
    const float* kng = (const float*)d_in[10];
    const float* knb = (const float*)d_in[11];
    float* out = (float*)d_out;

    __half* xh;
    __half* yh;
    __half* wqh;
    __half* wkvh;
    __half* woh;
    __half* atth;
    __half* qh;
    __half* kh;
    __half* vh;
    cudaGetSymbolAddress((void**)&xh, g_xh);
    cudaGetSymbolAddress((void**)&yh, g_yh);
    cudaGetSymbolAddress((void**)&wqh, g_wqh);
    cudaGetSymbolAddress((void**)&wkvh, g_wkvh);
    cudaGetSymbolAddress((void**)&woh, g_woh);
    cudaGetSymbolAddress((void**)&atth, g_atth);
    cudaGetSymbolAddress((void**)&qh, g_qh);
    cudaGetSymbolAddress((void**)&kh, g_kh);
    cudaGetSymbolAddress((void**)&vh, g_vh);

    // 0) convert inputs to fp16
    int n;
    n = BB * S1 * QD / 4;
    to_half<<<(n + 255) / 256, 256>>>(x, xh, n);
    n = BB * S2 * KVD / 4;
    to_half<<<(n + 255) / 256, 256>>>(y, yh, n);
    n = QD * QD / 4;
    to_half<<<(n + 255) / 256, 256>>>(wq, wqh, n);
    n = 2 * QD * KVD / 4;
    to_half<<<(n + 255) / 256, 256>>>(wkv, wkvh, n);
    n = QD * QD / 4;
    to_half<<<(n + 255) / 256, 256>>>(wo, woh, n);

    cudaFuncSetAttribute(gemm_q, cudaFuncAttributeMaxDynamicSharedMemorySize, GSM);
    cudaFuncSetAttribute(gemm_kv, cudaFuncAttributeMaxDynamicSharedMemorySize, GSM);
    cudaFuncSetAttribute(gemm_h, cudaFuncAttributeMaxDynamicSharedMemorySize, GSM);

    // 1) Q = LN(x @ wq^T + bq) + RoPE -> fp16
    gemm_q<<<dim3(QD / 128, (BB * S1) / 128), 256, GSM>>>(
        xh, wqh, bq, qh, qng, qnb, BB * S1, QD, QD);
    // 2) KV = y @ wkv^T + bkv; K->LN->fp16, V->fp16
    gemm_kv<<<dim3(KVD / 128, (BB * S2) / 128), 256, GSM>>>(
        yh, wkvh, bkv, kh, vh, kng, knb, BB * S2, KVD, KVD);
    // 3) tensor-core attention -> fp16
    cudaFuncSetAttribute(attn_mma, cudaFuncAttributeMaxDynamicSharedMemorySize, ASMEM);
    attn_mma<<<dim3(S1 / 64, BB * NH), 256, ASMEM>>>(qh, kh, vh, atth);
    // 4) out = att @ wo^T + bo
    gemm_h<<<dim3(QD / 128, (BB * S1) / 128), 256, GSM>>>(
        atth, woh, bo, out, BB * S1, QD, QD);
}